// round 14
// baseline (speedup 1.0000x reference)
#include <cuda_runtime.h>
#include <cuda_bf16.h>
#include <cstdint>

#define NN 50000
#define EE 800000
#define DD 128
#define HH 256
#define GG 512
#define LL 3
#define BN_EPS 1e-5f

#define MPAD 50048                 // NN rounded up to multiple of 128
#define MT_TILES (MPAD / 16)       // 3128 m16 tiles
#define GRID_ROWS (MPAD / 128)     // 391

// ---------------- scratch (static device globals; no allocation) -------------
__device__ float g_hin[NN * DD];
__device__ float g_zin[NN * DD];
__device__ float g_z1f[MPAD * HH];   // z1 in fragment order (fp32)
__device__ float g_z2[NN * DD];
__device__ float g_vn[GG * DD];
__device__ float g_pooled[GG * DD];
__device__ float g_tv1[GG * HH];
__device__ float g_tv2[GG * DD];
__device__ float g_sum[HH];
__device__ float g_sumsq[HH];
__device__ float g_scale[HH];
__device__ float g_shift[HH];
__device__ float g_scale2[DD];
__device__ float g_shift2[DD];

// CSR (built once per launch; graph constant across layers)
__device__ int g_deg[NN];
__device__ int g_start[NN];
__device__ int g_cursor[NN];
__device__ int g_counter;
__device__ int g_srcs[EE];
__device__ float g_easort[EE * 8];

// fragment-order bf16 scratch
__device__ uint4 g_fAH[MPAD * 256 / 8];
__device__ uint4 g_fAL[MPAD * 256 / 8];
__device__ uint2 g_fWH[16384];
__device__ uint2 g_fWL[16384];

// ---------------- helpers ----------------------------------------------------
__device__ __forceinline__ void atomic_add_f4(float* addr, float4 v) {
    asm volatile("red.global.add.v4.f32 [%0], {%1,%2,%3,%4};"
                 :: "l"(addr), "f"(v.x), "f"(v.y), "f"(v.z), "f"(v.w)
                 : "memory");
}

__device__ __forceinline__ void pack2_split(float x, float y, uint32_t& h, uint32_t& l) {
    __nv_bfloat162 hb = __floats2bfloat162_rn(x, y);
    float rx = x - __bfloat162float(hb.x);
    float ry = y - __bfloat162float(hb.y);
    __nv_bfloat162 lb = __floats2bfloat162_rn(rx, ry);
    h = *reinterpret_cast<uint32_t*>(&hb);
    l = *reinterpret_cast<uint32_t*>(&lb);
}

__device__ __forceinline__ void mma_bf16_v(float* d, const uint32_t* a, const uint32_t* b) {
    asm volatile(
        "mma.sync.aligned.m16n8k16.row.col.f32.bf16.bf16.f32 "
        "{%0,%1,%2,%3}, {%4,%5,%6,%7}, {%8,%9}, {%0,%1,%2,%3};"
        : "+f"(d[0]), "+f"(d[1]), "+f"(d[2]), "+f"(d[3])
        : "r"(a[0]), "r"(a[1]), "r"(a[2]), "r"(a[3]), "r"(b[0]), "r"(b[1]));
}

// ---------------- CSR build ----------------------------------------------------
__global__ void zero_deg_kernel(int* __restrict__ deg, int* __restrict__ counter, int n) {
    int i = blockIdx.x * blockDim.x + threadIdx.x;
    if (i < n) deg[i] = 0;
    if (i == 0) *counter = 0;
}

__global__ void hist_kernel(const int* __restrict__ dst, int* __restrict__ deg, int E) {
    int e = blockIdx.x * blockDim.x + threadIdx.x;
    if (e < E) atomicAdd(&deg[dst[e]], 1);
}

// per-block shared scan + one atomicAdd per block (segments non-monotonic, fine)
__global__ void __launch_bounds__(256) alloc_kernel(
    const int* __restrict__ deg, int* __restrict__ start, int* __restrict__ cursor,
    int* __restrict__ counter, int n)
{
    __shared__ int sh[256];
    __shared__ int sbase;
    const int t = threadIdx.x;
    const int i = blockIdx.x * 256 + t;
    const int d = (i < n) ? __ldg(deg + i) : 0;
    sh[t] = d;
    __syncthreads();
#pragma unroll
    for (int o = 1; o < 256; o <<= 1) {
        int v = (t >= o) ? sh[t - o] : 0;
        __syncthreads();
        sh[t] += v;
        __syncthreads();
    }
    if (t == 255) sbase = atomicAdd(counter, sh[255]);
    __syncthreads();
    if (i < n) {
        const int s = sbase + sh[t] - d;
        start[i] = s;
        cursor[i] = s;
    }
}

__global__ void scatter_kernel(const int* __restrict__ src, const int* __restrict__ dst,
                               const float* __restrict__ ea, int* __restrict__ cursor,
                               int* __restrict__ srcs, float* __restrict__ easort, int E)
{
    int e = blockIdx.x * blockDim.x + threadIdx.x;
    if (e >= E) return;
    const int d = dst[e];
    const int pos = atomicAdd(&cursor[d], 1);
    srcs[pos] = src[e];
    const float4 a0 = __ldg(reinterpret_cast<const float4*>(ea + (size_t)e * 8));
    const float4 a1 = __ldg(reinterpret_cast<const float4*>(ea + (size_t)e * 8 + 4));
    *reinterpret_cast<float4*>(easort + (size_t)pos * 8) = a0;
    *reinterpret_cast<float4*>(easort + (size_t)pos * 8 + 4) = a1;
}

// ---------------- CSR edge aggregation (atomic-free, pipelined gathers) -------
// warp per dst node: zin[d] = hin[d] + sum_j relu(hin[src_j] + MLP(ea_j))
// next pair's h-gathers issued one iteration ahead (clamped, warp-uniform)
__global__ void __launch_bounds__(256) edge_aggr_kernel(
    const float* __restrict__ easort, const float* __restrict__ We,
    const float* __restrict__ be, const float* __restrict__ hin,
    const int* __restrict__ srcs, const int* __restrict__ start,
    const int* __restrict__ deg, float* __restrict__ zin, int Nnodes)
{
    const int lane = threadIdx.x & 31;
    const int warp = (blockIdx.x * blockDim.x + threadIdx.x) >> 5;
    const int nwarps = (gridDim.x * blockDim.x) >> 5;

    float4 w[8];
#pragma unroll
    for (int k = 0; k < 8; k++)
        w[k] = __ldg(reinterpret_cast<const float4*>(We + k * DD + lane * 4));
    const float4 bb = __ldg(reinterpret_cast<const float4*>(be + lane * 4));

    for (int d = warp; d < Nnodes; d += nwarps) {
        const int o0 = __ldg(start + d);
        const int o1 = o0 + __ldg(deg + d);
        float4 acc = *reinterpret_cast<const float4*>(hin + (size_t)d * DD + lane * 4);
        const int npairs = (o1 - o0) >> 1;
        int j = o0;
        if (npairs > 0) {
            // prologue: gathers for pair 0
            int s0 = __ldg(srcs + j);
            int s1 = __ldg(srcs + j + 1);
            float4 hv0 = __ldg(reinterpret_cast<const float4*>(hin + (size_t)s0 * DD + lane * 4));
            float4 hv1 = __ldg(reinterpret_cast<const float4*>(hin + (size_t)s1 * DD + lane * 4));
            for (int p = 0; p < npairs; p++) {
                // prefetch next pair's gathers (clamped; warp-uniform, no divergence)
                const int pj = (j + 3 < o1) ? (j + 2) : j;
                const int ns0 = __ldg(srcs + pj);
                const int ns1 = __ldg(srcs + pj + 1);
                const float4 nhv0 = __ldg(reinterpret_cast<const float4*>(hin + (size_t)ns0 * DD + lane * 4));
                const float4 nhv1 = __ldg(reinterpret_cast<const float4*>(hin + (size_t)ns1 * DD + lane * 4));
                // edge-attr loads for current pair
                const float4 a00 = __ldg(reinterpret_cast<const float4*>(easort + (size_t)j * 8));
                const float4 a01 = __ldg(reinterpret_cast<const float4*>(easort + (size_t)j * 8 + 4));
                const float4 a10 = __ldg(reinterpret_cast<const float4*>(easort + (size_t)(j + 1) * 8));
                const float4 a11 = __ldg(reinterpret_cast<const float4*>(easort + (size_t)(j + 1) * 8 + 4));
                const float k0[8] = {a00.x, a00.y, a00.z, a00.w, a01.x, a01.y, a01.z, a01.w};
                const float k1[8] = {a10.x, a10.y, a10.z, a10.w, a11.x, a11.y, a11.z, a11.w};
                float4 e0 = bb, e1 = bb;
#pragma unroll
                for (int k = 0; k < 8; k++) {
                    e0.x = fmaf(k0[k], w[k].x, e0.x);
                    e0.y = fmaf(k0[k], w[k].y, e0.y);
                    e0.z = fmaf(k0[k], w[k].z, e0.z);
                    e0.w = fmaf(k0[k], w[k].w, e0.w);
                    e1.x = fmaf(k1[k], w[k].x, e1.x);
                    e1.y = fmaf(k1[k], w[k].y, e1.y);
                    e1.z = fmaf(k1[k], w[k].z, e1.z);
                    e1.w = fmaf(k1[k], w[k].w, e1.w);
                }
                acc.x += fmaxf(hv0.x + e0.x, 0.f) + fmaxf(hv1.x + e1.x, 0.f);
                acc.y += fmaxf(hv0.y + e0.y, 0.f) + fmaxf(hv1.y + e1.y, 0.f);
                acc.z += fmaxf(hv0.z + e0.z, 0.f) + fmaxf(hv1.z + e1.z, 0.f);
                acc.w += fmaxf(hv0.w + e0.w, 0.f) + fmaxf(hv1.w + e1.w, 0.f);
                j += 2;
                hv0 = nhv0;
                hv1 = nhv1;
            }
        }
        if ((o1 - o0) & 1) {
            const int jl = o1 - 1;
            const int s = __ldg(srcs + jl);
            const float4 hv = __ldg(reinterpret_cast<const float4*>(hin + (size_t)s * DD + lane * 4));
            const float4 a0 = __ldg(reinterpret_cast<const float4*>(easort + (size_t)jl * 8));
            const float4 a1 = __ldg(reinterpret_cast<const float4*>(easort + (size_t)jl * 8 + 4));
            const float ak[8] = {a0.x, a0.y, a0.z, a0.w, a1.x, a1.y, a1.z, a1.w};
            float4 e = bb;
#pragma unroll
            for (int k = 0; k < 8; k++) {
                e.x = fmaf(ak[k], w[k].x, e.x);
                e.y = fmaf(ak[k], w[k].y, e.y);
                e.z = fmaf(ak[k], w[k].z, e.z);
                e.w = fmaf(ak[k], w[k].w, e.w);
            }
            acc.x += fmaxf(hv.x + e.x, 0.f);
            acc.y += fmaxf(hv.y + e.y, 0.f);
            acc.z += fmaxf(hv.z + e.z, 0.f);
            acc.w += fmaxf(hv.w + e.w, 0.f);
        }
        *reinterpret_cast<float4*>(zin + (size_t)d * DD + lane * 4) = acc;
    }
}

// ---------------- fragment prep kernels ---------------------------------------
// row-major input; MODE 0: v = A1 + A2 ; MODE 2: v = A1
template <int MODE>
__global__ void __launch_bounds__(256) prep_A(
    const float* __restrict__ A1, const float* __restrict__ A2,
    uint4* __restrict__ FH, uint4* __restrict__ FL, int M, int K, int total)
{
    int idx = blockIdx.x * 256 + threadIdx.x;
    if (idx >= total) return;
    const int lane = idx & 31;
    const int tile = idx >> 5;
    const int KT = K >> 4;
    const int mt = tile / KT;
    const int kt = tile - mt * KT;
    const int g = lane >> 2;
    const int c = kt * 16 + (lane & 3) * 2;
    const int r0 = mt * 16 + g;

    float2 v[4];
    const int rr[4] = {r0, r0 + 8, r0, r0 + 8};
    const int cc[4] = {c, c, c + 8, c + 8};
#pragma unroll
    for (int i = 0; i < 4; i++) {
        float2 a = make_float2(0.f, 0.f);
        if (rr[i] < M) {
            const size_t off = (size_t)rr[i] * K + cc[i];
            a = *reinterpret_cast<const float2*>(A1 + off);
            if (MODE == 0) {
                const float2 b = *reinterpret_cast<const float2*>(A2 + off);
                a.x += b.x; a.y += b.y;
            }
        }
        v[i] = a;
    }
    uint4 hi, lo;
    pack2_split(v[0].x, v[0].y, hi.x, lo.x);
    pack2_split(v[1].x, v[1].y, hi.y, lo.y);
    pack2_split(v[2].x, v[2].y, hi.z, lo.z);
    pack2_split(v[3].x, v[3].y, hi.w, lo.w);
    FH[tile * 32 + lane] = hi;
    FL[tile * 32 + lane] = lo;
}

// fragment-order input (z1f): apply relu(scale*z+shift), split to bf16 hi/lo.
__global__ void __launch_bounds__(256) prep_A_frag(
    const float4* __restrict__ Zf, const float* __restrict__ sc,
    const float* __restrict__ sh, uint4* __restrict__ FH, uint4* __restrict__ FL,
    int NT, int total)
{
    int idx = blockIdx.x * 256 + threadIdx.x;
    if (idx >= total) return;
    const int lane = idx & 31;
    const int tile = idx >> 5;
    const int KT = NT >> 1;
    const int mt = tile / KT;
    const int kt = tile - mt * KT;
    const int c0 = kt * 16 + (lane & 3) * 2;

    float4 v0 = __ldg(&Zf[((size_t)mt * NT + 2 * kt) * 32 + lane]);
    float4 v1 = __ldg(&Zf[((size_t)mt * NT + 2 * kt + 1) * 32 + lane]);
    const float2 s0 = *reinterpret_cast<const float2*>(sc + c0);
    const float2 t0 = *reinterpret_cast<const float2*>(sh + c0);
    const float2 s1 = *reinterpret_cast<const float2*>(sc + c0 + 8);
    const float2 t1 = *reinterpret_cast<const float2*>(sh + c0 + 8);
    v0.x = fmaxf(fmaf(s0.x, v0.x, t0.x), 0.f);
    v0.y = fmaxf(fmaf(s0.y, v0.y, t0.y), 0.f);
    v0.z = fmaxf(fmaf(s0.x, v0.z, t0.x), 0.f);
    v0.w = fmaxf(fmaf(s0.y, v0.w, t0.y), 0.f);
    v1.x = fmaxf(fmaf(s1.x, v1.x, t1.x), 0.f);
    v1.y = fmaxf(fmaf(s1.y, v1.y, t1.y), 0.f);
    v1.z = fmaxf(fmaf(s1.x, v1.z, t1.x), 0.f);
    v1.w = fmaxf(fmaf(s1.y, v1.w, t1.y), 0.f);

    uint4 hi, lo;
    pack2_split(v0.x, v0.y, hi.x, lo.x);
    pack2_split(v0.z, v0.w, hi.y, lo.y);
    pack2_split(v1.x, v1.y, hi.z, lo.z);
    pack2_split(v1.z, v1.w, hi.w, lo.w);
    FH[tile * 32 + lane] = hi;
    FL[tile * 32 + lane] = lo;
}

__global__ void __launch_bounds__(256) prep_W(
    const float* __restrict__ W, uint2* __restrict__ FH, uint2* __restrict__ FL,
    int F, int KT, int total)
{
    int idx = blockIdx.x * 256 + threadIdx.x;
    if (idx >= total) return;
    const int lane = idx & 31;
    const int tile = idx >> 5;
    const int nt = tile / KT;
    const int kt = tile - nt * KT;
    const int n = nt * 8 + (lane >> 2);
    const int k0 = kt * 16 + (lane & 3) * 2;
    const float p00 = __ldg(W + (size_t)k0 * F + n);
    const float p01 = __ldg(W + (size_t)(k0 + 1) * F + n);
    const float p10 = __ldg(W + (size_t)(k0 + 8) * F + n);
    const float p11 = __ldg(W + (size_t)(k0 + 9) * F + n);
    uint2 hi, lo;
    pack2_split(p00, p01, hi.x, lo.x);
    pack2_split(p10, p11, hi.y, lo.y);
    FH[tile * 32 + lane] = hi;
    FL[tile * 32 + lane] = lo;
}

// ---------------- fragment-direct tensor-core GEMM ----------------------------
// FRAGOUT=1: store C in fragment order (float4 per lane per m16n8 tile)
template <int FDIM, int FRAGOUT>
__global__ void __launch_bounds__(256) frag_gemm(
    const uint4* __restrict__ AH, const uint4* __restrict__ AL,
    const uint2* __restrict__ BH, const uint2* __restrict__ BL,
    const float* __restrict__ bias, float* __restrict__ C, int M, int KT)
{
    const int lane = threadIdx.x & 31;
    const int wid = threadIdx.x >> 5;
    const int warp_m = wid & 3;
    const int warp_n = wid >> 2;
    const int mt0 = blockIdx.y * 8 + warp_m * 2;
    const int nt0 = blockIdx.x * 16 + warp_n * 8;

    float acc[2][8][4];
#pragma unroll
    for (int i = 0; i < 2; i++)
#pragma unroll
        for (int j = 0; j < 8; j++)
#pragma unroll
            for (int q = 0; q < 4; q++) acc[i][j][q] = 0.f;

    for (int kt = 0; kt < KT; kt++) {
        uint4 ah[2], al[2];
#pragma unroll
        for (int im = 0; im < 2; im++) {
            const size_t aidx = ((size_t)(mt0 + im) * KT + kt) * 32 + lane;
            ah[im] = __ldg(&AH[aidx]);
            al[im] = __ldg(&AL[aidx]);
        }
        uint2 bh[8], bl[8];
#pragma unroll
        for (int nb = 0; nb < 8; nb++) {
            const size_t bidx = ((size_t)(nt0 + nb) * KT + kt) * 32 + lane;
            bh[nb] = __ldg(&BH[bidx]);
            bl[nb] = __ldg(&BL[bidx]);
        }
#pragma unroll
        for (int im = 0; im < 2; im++)
#pragma unroll
            for (int nb = 0; nb < 8; nb++) {
                mma_bf16_v(acc[im][nb], reinterpret_cast<const uint32_t*>(&ah[im]),
                           reinterpret_cast<const uint32_t*>(&bh[nb]));
                mma_bf16_v(acc[im][nb], reinterpret_cast<const uint32_t*>(&ah[im]),
                           reinterpret_cast<const uint32_t*>(&bl[nb]));
                mma_bf16_v(acc[im][nb], reinterpret_cast<const uint32_t*>(&al[im]),
                           reinterpret_cast<const uint32_t*>(&bh[nb]));
            }
    }

    const int gid = lane >> 2;
    const int tig = lane & 3;
    if (FRAGOUT) {
        const int NT = FDIM / 8;
#pragma unroll
        for (int im = 0; im < 2; im++) {
            const int mt = mt0 + im;
#pragma unroll
            for (int nb = 0; nb < 8; nb++) {
                const int ntg = nt0 + nb;
                const int col = ntg * 8 + tig * 2;
                const float2 bv = *reinterpret_cast<const float2*>(bias + col);
                float4 o = make_float4(acc[im][nb][0] + bv.x, acc[im][nb][1] + bv.y,
                                       acc[im][nb][2] + bv.x, acc[im][nb][3] + bv.y);
                *reinterpret_cast<float4*>(C + (((size_t)mt * NT + ntg) * 32 + lane) * 4) = o;
            }
        }
    } else {
#pragma unroll
        for (int im = 0; im < 2; im++) {
            const int rbase = blockIdx.y * 128 + warp_m * 32 + im * 16;
            const int r0 = rbase + gid;
            const int r1 = r0 + 8;
#pragma unroll
            for (int nb = 0; nb < 8; nb++) {
                const int col = blockIdx.x * 128 + warp_n * 64 + nb * 8 + tig * 2;
                const float2 bv = *reinterpret_cast<const float2*>(bias + col);
                if (r0 < M) {
                    float2 o = make_float2(acc[im][nb][0] + bv.x, acc[im][nb][1] + bv.y);
                    *reinterpret_cast<float2*>(C + (size_t)r0 * FDIM + col) = o;
                }
                if (r1 < M) {
                    float2 o = make_float2(acc[im][nb][2] + bv.x, acc[im][nb][3] + bv.y);
                    *reinterpret_cast<float2*>(C + (size_t)r1 * FDIM + col) = o;
                }
            }
        }
    }
}

// ---------------- stats over fragment-order buffer -----------------------------
__global__ void __launch_bounds__(256) stats_frag_kernel(
    const float4* __restrict__ Zf, int M, int NT,
    float* __restrict__ gsum, float* __restrict__ gsq)
{
    const int nb = blockIdx.x;
    const int lane = threadIdx.x & 31;
    const int w = threadIdx.x >> 5;          // 8 warps
    const int tig = lane & 3;
    const int g = lane >> 2;
    const int mtfull = M >> 4;
    const int rem = M & 15;
    float s0 = 0.f, s1 = 0.f, q0 = 0.f, q1 = 0.f;
    for (int mt = blockIdx.y * 8 + w; mt < mtfull; mt += gridDim.y * 8) {
        const float4 v = __ldg(&Zf[((size_t)mt * NT + nb) * 32 + lane]);
        s0 += v.x + v.z; q0 = fmaf(v.x, v.x, fmaf(v.z, v.z, q0));
        s1 += v.y + v.w; q1 = fmaf(v.y, v.y, fmaf(v.w, v.w, q1));
    }
    if (rem && blockIdx.y == 0 && w == 0) {
        const float4 v = __ldg(&Zf[((size_t)mtfull * NT + nb) * 32 + lane]);
        if (g < rem)     { s0 += v.x; q0 = fmaf(v.x, v.x, q0); s1 += v.y; q1 = fmaf(v.y, v.y, q1); }
        if (g + 8 < rem) { s0 += v.z; q0 = fmaf(v.z, v.z, q0); s1 += v.w; q1 = fmaf(v.w, v.w, q1); }
    }
#pragma unroll
    for (int off = 4; off < 32; off <<= 1) {
        s0 += __shfl_xor_sync(0xffffffffu, s0, off);
        s1 += __shfl_xor_sync(0xffffffffu, s1, off);
        q0 += __shfl_xor_sync(0xffffffffu, q0, off);
        q1 += __shfl_xor_sync(0xffffffffu, q1, off);
    }
    __shared__ float sm[8][4][4];
    if (lane < 4) {
        sm[w][tig][0] = s0; sm[w][tig][1] = s1;
        sm[w][tig][2] = q0; sm[w][tig][3] = q1;
    }
    __syncthreads();
    if (threadIdx.x < 4) {
        const int t = threadIdx.x;
        float S0 = 0.f, S1 = 0.f, Q0 = 0.f, Q1 = 0.f;
#pragma unroll
        for (int ww = 0; ww < 8; ww++) {
            S0 += sm[ww][t][0]; S1 += sm[ww][t][1];
            Q0 += sm[ww][t][2]; Q1 += sm[ww][t][3];
        }
        const int col = nb * 8 + t * 2;
        atomicAdd(&gsum[col], S0);
        atomicAdd(&gsum[col + 1], S1);
        atomicAdd(&gsq[col], Q0);
        atomicAdd(&gsq[col + 1], Q1);
    }
}

// ---------------- elementwise / misc kernels ----------------------------------
__global__ void zero_kernel(float4* __restrict__ a, int n4) {
    int idx = blockIdx.x * blockDim.x + threadIdx.x;
    if (idx < n4) a[idx] = make_float4(0.f, 0.f, 0.f, 0.f);
}

__global__ void init_vn_kernel(const float* __restrict__ vn_emb, float* __restrict__ vn,
                               float* __restrict__ s, float* __restrict__ q) {
    int idx = blockIdx.x * blockDim.x + threadIdx.x;
    if (idx < GG * DD) vn[idx] = vn_emb[idx & (DD - 1)];
    if (idx < HH) { s[idx] = 0.f; q[idx] = 0.f; }
}

// h_in = op(A) + vn[batch];  POOL: pooled[batch] += h_in
template <int MODE, int POOL>
__global__ void hin_kernel(const float* __restrict__ A,
                           const float* __restrict__ sc, const float* __restrict__ sh,
                           const float* __restrict__ vn, const int* __restrict__ batch,
                           float* __restrict__ hin, float* __restrict__ pooled, int n) {
    int idx = blockIdx.x * blockDim.x + threadIdx.x;
    int total = n * (DD / 4);
    if (idx >= total) return;
    int row = idx >> 5;
    int c4 = (idx & 31) << 2;
    int g = batch[row];
    float4 a = *reinterpret_cast<const float4*>(A + (size_t)row * DD + c4);
    if (MODE == 1) {
        const float4 s = __ldg(reinterpret_cast<const float4*>(sc + c4));
        const float4 t = __ldg(reinterpret_cast<const float4*>(sh + c4));
        a.x = fmaxf(fmaf(s.x, a.x, t.x), 0.f);
        a.y = fmaxf(fmaf(s.y, a.y, t.y), 0.f);
        a.z = fmaxf(fmaf(s.z, a.z, t.z), 0.f);
        a.w = fmaxf(fmaf(s.w, a.w, t.w), 0.f);
    }
    const float4 b = *reinterpret_cast<const float4*>(vn + (size_t)g * DD + c4);
    float4 o = make_float4(a.x + b.x, a.y + b.y, a.z + b.z, a.w + b.w);
    *reinterpret_cast<float4*>(hin + (size_t)row * DD + c4) = o;
    if (POOL) atomic_add_f4(pooled + (size_t)g * DD + c4, o);
}

// SIMT GEMM for the tiny virtual-node MLPs (512 rows)
template <int MODE>
__global__ void __launch_bounds__(256) gemm_kernel(
    const float* __restrict__ A1, const float* __restrict__ A2,
    const float* __restrict__ bnscale, const float* __restrict__ bnshift,
    const float* __restrict__ B, const float* __restrict__ bias,
    float* __restrict__ C, int M, int K, int F)
{
    const int BM = 128, BN = 128, BK = 16;
    __shared__ float sA[BK][BM];
    __shared__ float sB[BK][BN];
    int tid = threadIdx.x;
    int brow = blockIdx.y * BM;
    int bcol = blockIdx.x * BN;

    float acc[8][8];
#pragma unroll
    for (int i = 0; i < 8; i++)
#pragma unroll
        for (int j = 0; j < 8; j++) acc[i][j] = 0.f;

    int tr = (tid >> 4) << 3;
    int tc = (tid & 15) << 3;

    for (int k0 = 0; k0 < K; k0 += BK) {
#pragma unroll
        for (int i = 0; i < 2; i++) {
            int idx = tid + i * 256;
            int r = idx >> 2;
            int c4 = (idx & 3) << 2;
            int row = brow + r;
            float4 v = make_float4(0.f, 0.f, 0.f, 0.f);
            if (row < M) {
                size_t off = (size_t)row * K + k0 + c4;
                if (MODE == 0) {
                    float4 a = __ldg(reinterpret_cast<const float4*>(A1 + off));
                    float4 b = __ldg(reinterpret_cast<const float4*>(A2 + off));
                    v = make_float4(a.x + b.x, a.y + b.y, a.z + b.z, a.w + b.w);
                } else {
                    float4 a = __ldg(reinterpret_cast<const float4*>(A1 + off));
                    float4 s = __ldg(reinterpret_cast<const float4*>(bnscale + k0 + c4));
                    float4 t = __ldg(reinterpret_cast<const float4*>(bnshift + k0 + c4));
                    v.x = fmaxf(fmaf(s.x, a.x, t.x), 0.f);
                    v.y = fmaxf(fmaf(s.y, a.y, t.y), 0.f);
                    v.z = fmaxf(fmaf(s.z, a.z, t.z), 0.f);
                    v.w = fmaxf(fmaf(s.w, a.w, t.w), 0.f);
                }
            }
            sA[c4 + 0][r] = v.x;
            sA[c4 + 1][r] = v.y;
            sA[c4 + 2][r] = v.z;
            sA[c4 + 3][r] = v.w;
        }
#pragma unroll
        for (int i = 0; i < 2; i++) {
            int idx = tid + i * 256;
            int r = idx >> 5;
            int c4 = (idx & 31) << 2;
            float4 v = __ldg(reinterpret_cast<const float4*>(B + (size_t)(k0 + r) * F + bcol + c4));
            *reinterpret_cast<float4*>(&sB[r][c4]) = v;
        }
        __syncthreads();
#pragma unroll
        for (int kk = 0; kk < BK; kk++) {
            float a[8], b[8];
            *reinterpret_cast<float4*>(&a[0]) = *reinterpret_cast<float4*>(&sA[kk][tr]);
            *reinterpret_cast<float4*>(&a[4]) = *reinterpret_cast<float4*>(&sA[kk][tr + 4]);
            *reinterpret_cast<float4*>(&b[0]) = *reinterpret_cast<float4*>(&sB[kk][tc]);
            *reinterpret_cast<float4*>(&b[4]) = *reinterpret_cast<float4*>(&sB[kk][tc + 4]);
#pragma unroll
            for (int i = 0; i < 8; i++)
#pragma unroll
                for (int j = 0; j < 8; j++)
                    acc[i][j] = fmaf(a[i], b[j], acc[i][j]);
        }
        __syncthreads();
    }
#pragma unroll
    for (int i = 0; i < 8; i++) {
        int row = brow + tr + i;
        if (row < M) {
#pragma unroll
            for (int j = 0; j < 8; j += 4) {
                float4 bv = __ldg(reinterpret_cast<const float4*>(bias + bcol + tc + j));
                float4 o;
                o.x = acc[i][j + 0] + bv.x;
                o.y = acc[i][j + 1] + bv.y;
                o.z = acc[i][j + 2] + bv.z;
                o.w = acc[i][j + 3] + bv.w;
                *reinterpret_cast<float4*>(C + (size_t)row * F + bcol + tc + j) = o;
            }
        }
    }
}

__global__ void stats_kernel(const float* __restrict__ Z, int M, int F,
                             float* __restrict__ gsum, float* __restrict__ gsq) {
    int col = threadIdx.x;
    int r0 = blockIdx.x * 128;
    int rend = min(r0 + 128, M);
    float s = 0.f, q = 0.f;
    for (int r = r0; r < rend; r++) {
        float v = Z[(size_t)r * F + col];
        s += v;
        q = fmaf(v, v, q);
    }
    atomicAdd(&gsum[col], s);
    atomicAdd(&gsq[col], q);
}

// consume stats, produce scale/shift, then zero the accumulators for reuse
__global__ void bn_finalize_kernel(float* __restrict__ gsum, float* __restrict__ gsq,
                                   const float* __restrict__ gamma, const float* __restrict__ beta,
                                   int M, float* __restrict__ scale, float* __restrict__ shift) {
    int f = threadIdx.x;
    float invM = 1.f / (float)M;
    float mean = gsum[f] * invM;
    float var = gsq[f] * invM - mean * mean;
    float inv = rsqrtf(var + BN_EPS);
    float sc = gamma[f] * inv;
    scale[f] = sc;
    shift[f] = beta[f] - mean * sc;
    gsum[f] = 0.f;
    gsq[f] = 0.f;
}

__global__ void bn_apply_kernel(const float* __restrict__ Z, const float* __restrict__ scale,
                                const float* __restrict__ shift, float* __restrict__ out,
                                int M, int F, int do_relu) {
    int idx = blockIdx.x * blockDim.x + threadIdx.x;
    int total = M * (F >> 2);
    if (idx >= total) return;
    int cols4 = F >> 2;
    int row = idx / cols4;
    int c4 = (idx - row * cols4) << 2;
    float4 z = *reinterpret_cast<const float4*>(Z + (size_t)row * F + c4);
    float4 s = __ldg(reinterpret_cast<const float4*>(scale + c4));
    float4 t = __ldg(reinterpret_cast<const float4*>(shift + c4));
    float4 o;
    o.x = fmaf(s.x, z.x, t.x);
    o.y = fmaf(s.y, z.y, t.y);
    o.z = fmaf(s.z, z.z, t.z);
    o.w = fmaf(s.w, z.w, t.w);
    if (do_relu) {
        o.x = fmaxf(o.x, 0.f);
        o.y = fmaxf(o.y, 0.f);
        o.z = fmaxf(o.z, 0.f);
        o.w = fmaxf(o.w, 0.f);
    }
    *reinterpret_cast<float4*>(out + (size_t)row * F + c4) = o;
}

// ------------------------------ host driver ----------------------------------
static inline int cdiv(int a, int b) { return (a + b - 1) / b; }

extern "C" void kernel_launch(void* const* d_in, const int* in_sizes, int n_in,
                              void* d_out, int out_size) {
    const float* x        = (const float*)d_in[0];
    const float* edge_attr= (const float*)d_in[1];
    const float* vn_emb   = (const float*)d_in[2];
    const float* We   = (const float*)d_in[3];
    const float* be   = (const float*)d_in[4];
    const float* W1   = (const float*)d_in[5];
    const float* b1   = (const float*)d_in[6];
    const float* g1   = (const float*)d_in[7];
    const float* bt1  = (const float*)d_in[8];
    const float* W2   = (const float*)d_in[9];
    const float* b2   = (const float*)d_in[10];
    const float* gb   = (const float*)d_in[11];
    const float* bbp  = (const float*)d_in[12];
    const float* Wv1  = (const float*)d_in[13];
    const float* bv1  = (const float*)d_in[14];
    const float* gv1  = (const float*)d_in[15];
    const float* btv1 = (const float*)d_in[16];
    const float* Wv2  = (const float*)d_in[17];
    const float* bv2  = (const float*)d_in[18];
    const float* gv2  = (const float*)d_in[19];
    const float* btv2 = (const float*)d_in[20];
    const int* edge_index = (const int*)d_in[21];
    const int* batch      = (const int*)d_in[22];

    const int N = in_sizes[0] / DD;
    const int E = in_sizes[1] / 8;
    const int* srcp = edge_index;
    const int* dstp = edge_index + E;
    float* out = (float*)d_out;

    float *p_hin, *p_zin, *p_z1f, *p_z2, *p_vn, *p_pooled, *p_tv1, *p_tv2;
    float *p_sum, *p_sq, *p_scale, *p_shift, *p_scale2, *p_shift2, *p_easort;
    int *p_deg, *p_start, *p_cursor, *p_counter, *p_srcs;
    uint4 *p_fAH, *p_fAL;
    uint2 *p_fWH, *p_fWL;
    cudaGetSymbolAddress((void**)&p_hin, g_hin);
    cudaGetSymbolAddress((void**)&p_zin, g_zin);
    cudaGetSymbolAddress((void**)&p_z1f, g_z1f);
    cudaGetSymbolAddress((void**)&p_z2, g_z2);
    cudaGetSymbolAddress((void**)&p_vn, g_vn);
    cudaGetSymbolAddress((void**)&p_pooled, g_pooled);
    cudaGetSymbolAddress((void**)&p_tv1, g_tv1);
    cudaGetSymbolAddress((void**)&p_tv2, g_tv2);
    cudaGetSymbolAddress((void**)&p_sum, g_sum);
    cudaGetSymbolAddress((void**)&p_sq, g_sumsq);
    cudaGetSymbolAddress((void**)&p_scale, g_scale);
    cudaGetSymbolAddress((void**)&p_shift, g_shift);
    cudaGetSymbolAddress((void**)&p_scale2, g_scale2);
    cudaGetSymbolAddress((void**)&p_shift2, g_shift2);
    cudaGetSymbolAddress((void**)&p_easort, g_easort);
    cudaGetSymbolAddress((void**)&p_deg, g_deg);
    cudaGetSymbolAddress((void**)&p_start, g_start);
    cudaGetSymbolAddress((void**)&p_cursor, g_cursor);
    cudaGetSymbolAddress((void**)&p_counter, g_counter);
    cudaGetSymbolAddress((void**)&p_srcs, g_srcs);
    cudaGetSymbolAddress((void**)&p_fAH, g_fAH);
    cudaGetSymbolAddress((void**)&p_fAL, g_fAL);
    cudaGetSymbolAddress((void**)&p_fWH, g_fWH);
    cudaGetSymbolAddress((void**)&p_fWL, g_fWL);

    // ---- one-time per call: init vn + stats accumulators + CSR build ----
    init_vn_kernel<<<cdiv(GG * DD, 256), 256>>>(vn_emb, p_vn, p_sum, p_sq);
    zero_deg_kernel<<<cdiv(N, 256), 256>>>(p_deg, p_counter, N);
    hist_kernel<<<cdiv(E, 256), 256>>>(dstp, p_deg, E);
    alloc_kernel<<<cdiv(N, 256), 256>>>(p_deg, p_start, p_cursor, p_counter, N);
    scatter_kernel<<<cdiv(E, 256), 256>>>(srcp, dstp, edge_attr, p_cursor,
                                          p_srcs, p_easort, E);

    const int nf4 = N * (DD / 4);

    for (int l = 0; l < LL; l++) {
        const int need_pool = (l < LL - 1);
        if (need_pool)
            zero_kernel<<<cdiv(GG * DD / 4, 256), 256>>>((float4*)p_pooled, GG * DD / 4);
        // h_in = op(prev) + vn[batch]; pooled[batch] += h_in
        if (l == 0) {
            if (need_pool)
                hin_kernel<0, 1><<<cdiv(nf4, 256), 256>>>(x, nullptr, nullptr, p_vn, batch,
                                                          p_hin, p_pooled, N);
            else
                hin_kernel<0, 0><<<cdiv(nf4, 256), 256>>>(x, nullptr, nullptr, p_vn, batch,
                                                          p_hin, p_pooled, N);
        } else {
            if (need_pool)
                hin_kernel<1, 1><<<cdiv(nf4, 256), 256>>>(p_z2, p_scale2, p_shift2, p_vn, batch,
                                                          p_hin, p_pooled, N);
            else
                hin_kernel<1, 0><<<cdiv(nf4, 256), 256>>>(p_z2, p_scale2, p_shift2, p_vn, batch,
                                                          p_hin, p_pooled, N);
        }
        // zin = h_in + sum_edges relu(h_in[src] + MLP(ea))   (atomic-free CSR)
        edge_aggr_kernel<<<2048, 256>>>(p_easort, We + (size_t)l * 8 * DD,
                                        be + (size_t)l * DD, p_hin, p_srcs, p_start,
                                        p_deg, p_zin, N);

        // ---- z1f = zin @ W1 + b1  (fragment-order output)  [N x HH], K=DD ----
        {
            const int KT = DD / 16;
            const int wtot = (HH / 8) * KT * 32;
            prep_W<<<cdiv(wtot, 256), 256>>>(W1 + (size_t)l * DD * HH, p_fWH, p_fWL, HH, KT, wtot);
            const int atot = MT_TILES * KT * 32;
            prep_A<2><<<cdiv(atot, 256), 256>>>(p_zin, nullptr, p_fAH, p_fAL, N, DD, atot);
            dim3 grid(HH / 128, GRID_ROWS);
            frag_gemm<HH, 1><<<grid, 256>>>(p_fAH, p_fAL, p_fWH, p_fWL,
                                            b1 + (size_t)l * HH, p_z1f, N, KT);
        }
        {
            dim3 sgrid(HH / 8, 8);
            stats_frag_kernel<<<sgrid, 256>>>((const float4*)p_z1f, N, HH / 8, p_sum, p_sq);
        }
        bn_finalize_kernel<<<1, HH>>>(p_sum, p_sq, g1 + (size_t)l * HH, bt1 + (size_t)l * HH,
                                      N, p_scale, p_shift);

        // ---- z2 = relu(BN(z1)) @ W2 + b2    [N x DD], K=HH ----
        {
            const int KT = HH / 16;
            const int wtot = (DD / 8) * KT * 32;
            prep_W<<<cdiv(wtot, 256), 256>>>(W2 + (size_t)l * HH * DD, p_fWH, p_fWL, DD, KT, wtot);
            const int atot = MT_TILES * KT * 32;
            prep_A_frag<<<cdiv(atot, 256), 256>>>((const float4*)p_z1f, p_scale, p_shift,
                                                  p_fAH, p_fAL, HH / 8, atot);
            dim3 grid(DD / 128, GRID_ROWS);
            frag_gemm<DD, 0><<<grid, 256>>>(p_fAH, p_fAL, p_fWH, p_fWL,
                                            b2 + (size_t)l * DD, p_z2, N, KT);
        }
        stats_kernel<<<cdiv(N, 128), DD>>>(p_z2, N, DD, p_sum, p_sq);
        bn_finalize_kernel<<<1, DD>>>(p_sum, p_sq, gb + (size_t)l * DD, bbp + (size_t)l * DD,
                                      N, p_scale2, p_shift2);

        if (l < LL - 1) {
            // ---- virtual node update (tiny, SIMT path) ----
            {
                dim3 grid(HH / 128, cdiv(GG, 128));
                gemm_kernel<0><<<grid, 256>>>(p_pooled, p_vn, nullptr, nullptr,
                                              Wv1 + (size_t)l * DD * HH, bv1 + (size_t)l * HH,
                                              p_tv1, GG, DD, HH);
            }
            stats_kernel<<<cdiv(GG, 128), HH>>>(p_tv1, GG, HH, p_sum, p_sq);
            bn_finalize_kernel<<<1, HH>>>(p_sum, p_sq, gv1 + (size_t)l * HH, btv1 + (size_t)l * HH,
                                          GG, p_scale, p_shift);
            {
                dim3 grid(DD / 128, cdiv(GG, 128));
                gemm_kernel<1><<<grid, 256>>>(p_tv1, nullptr, p_scale, p_shift,
                                              Wv2 + (size_t)l * HH * DD, bv2 + (size_t)l * DD,
                                              p_tv2, GG, HH, DD);
            }
            stats_kernel<<<cdiv(GG, 128), DD>>>(p_tv2, GG, DD, p_sum, p_sq);
            bn_finalize_kernel<<<1, DD>>>(p_sum, p_sq, gv2 + (size_t)l * DD, btv2 + (size_t)l * DD,
                                          GG, p_scale, p_shift);
            bn_apply_kernel<<<cdiv(GG * DD / 4, 256), 256>>>(p_tv2, p_scale, p_shift, p_vn,
                                                             GG, DD, 1);
        } else {
            bn_apply_kernel<<<cdiv(nf4, 256), 256>>>(p_z2, p_scale2, p_shift2, out, N, DD, 0);
        }
    }
}

// round 15
// speedup vs baseline: 1.1156x; 1.1156x over previous
#include <cuda_runtime.h>
#include <cuda_bf16.h>
#include <cstdint>

#define NN 50000
#define EE 800000
#define DD 128
#define HH 256
#define GG 512
#define LL 3
#define BN_EPS 1e-5f

#define MPAD 50048                 // NN rounded up to multiple of 128
#define MT_TILES (MPAD / 16)       // 3128 m16 tiles
#define GRID_ROWS (MPAD / 128)     // 391

// ---------------- scratch (static device globals; no allocation) -------------
__device__ float g_hin[NN * DD];
__device__ float g_zin[NN * DD];
__device__ float g_z1f[MPAD * HH];   // z1 in fragment order (fp32)
__device__ float g_z2[NN * DD];
__device__ float g_vn[GG * DD];
__device__ float g_pooled[GG * DD];
__device__ float g_tv1[GG * HH];
__device__ float g_tv2[GG * DD];
__device__ float g_sum[HH];
__device__ float g_sumsq[HH];
__device__ float g_scale[HH];
__device__ float g_shift[HH];
__device__ float g_scale2[DD];
__device__ float g_shift2[DD];

// CSR (built once per launch; graph constant across layers)
__device__ int g_deg[NN];
__device__ int g_start[NN];
__device__ int g_cursor[NN];
__device__ int g_counter;
__device__ int g_srcs[EE];
__device__ float g_easort[EE * 8];

// fragment-order bf16 scratch
__device__ uint4 g_fAH[MPAD * 256 / 8];
__device__ uint4 g_fAL[MPAD * 256 / 8];
__device__ uint2 g_fWH[16384];
__device__ uint2 g_fWL[16384];

// ---------------- helpers ----------------------------------------------------
__device__ __forceinline__ void atomic_add_f4(float* addr, float4 v) {
    asm volatile("red.global.add.v4.f32 [%0], {%1,%2,%3,%4};"
                 :: "l"(addr), "f"(v.x), "f"(v.y), "f"(v.z), "f"(v.w)
                 : "memory");
}

__device__ __forceinline__ void pack2_split(float x, float y, uint32_t& h, uint32_t& l) {
    __nv_bfloat162 hb = __floats2bfloat162_rn(x, y);
    float rx = x - __bfloat162float(hb.x);
    float ry = y - __bfloat162float(hb.y);
    __nv_bfloat162 lb = __floats2bfloat162_rn(rx, ry);
    h = *reinterpret_cast<uint32_t*>(&hb);
    l = *reinterpret_cast<uint32_t*>(&lb);
}

__device__ __forceinline__ void mma_bf16_v(float* d, const uint32_t* a, const uint32_t* b) {
    asm volatile(
        "mma.sync.aligned.m16n8k16.row.col.f32.bf16.bf16.f32 "
        "{%0,%1,%2,%3}, {%4,%5,%6,%7}, {%8,%9}, {%0,%1,%2,%3};"
        : "+f"(d[0]), "+f"(d[1]), "+f"(d[2]), "+f"(d[3])
        : "r"(a[0]), "r"(a[1]), "r"(a[2]), "r"(a[3]), "r"(b[0]), "r"(b[1]));
}

// ---------------- CSR build ----------------------------------------------------
__global__ void zero_deg_kernel(int* __restrict__ deg, int* __restrict__ counter, int n) {
    int i = blockIdx.x * blockDim.x + threadIdx.x;
    if (i < n) deg[i] = 0;
    if (i == 0) *counter = 0;
}

__global__ void hist_kernel(const int* __restrict__ dst, int* __restrict__ deg, int E) {
    int e = blockIdx.x * blockDim.x + threadIdx.x;
    if (e < E) atomicAdd(&deg[dst[e]], 1);
}

// per-block shared scan + one atomicAdd per block (segments non-monotonic, fine)
__global__ void __launch_bounds__(256) alloc_kernel(
    const int* __restrict__ deg, int* __restrict__ start, int* __restrict__ cursor,
    int* __restrict__ counter, int n)
{
    __shared__ int sh[256];
    __shared__ int sbase;
    const int t = threadIdx.x;
    const int i = blockIdx.x * 256 + t;
    const int d = (i < n) ? __ldg(deg + i) : 0;
    sh[t] = d;
    __syncthreads();
#pragma unroll
    for (int o = 1; o < 256; o <<= 1) {
        int v = (t >= o) ? sh[t - o] : 0;
        __syncthreads();
        sh[t] += v;
        __syncthreads();
    }
    if (t == 255) sbase = atomicAdd(counter, sh[255]);
    __syncthreads();
    if (i < n) {
        const int s = sbase + sh[t] - d;
        start[i] = s;
        cursor[i] = s;
    }
}

__global__ void scatter_kernel(const int* __restrict__ src, const int* __restrict__ dst,
                               const float* __restrict__ ea, int* __restrict__ cursor,
                               int* __restrict__ srcs, float* __restrict__ easort, int E)
{
    int e = blockIdx.x * blockDim.x + threadIdx.x;
    if (e >= E) return;
    const int d = dst[e];
    const int pos = atomicAdd(&cursor[d], 1);
    srcs[pos] = src[e];
    const float4 a0 = __ldg(reinterpret_cast<const float4*>(ea + (size_t)e * 8));
    const float4 a1 = __ldg(reinterpret_cast<const float4*>(ea + (size_t)e * 8 + 4));
    *reinterpret_cast<float4*>(easort + (size_t)pos * 8) = a0;
    *reinterpret_cast<float4*>(easort + (size_t)pos * 8 + 4) = a1;
}

// ---------------- CSR edge aggregation (atomic-free, unroll-2, reg weights) ---
// warp per dst node: zin[d] = hin[d] + sum_j relu(hin[src_j] + MLP(ea_j))
__global__ void __launch_bounds__(256) edge_aggr_kernel(
    const float* __restrict__ easort, const float* __restrict__ We,
    const float* __restrict__ be, const float* __restrict__ hin,
    const int* __restrict__ srcs, const int* __restrict__ start,
    const int* __restrict__ deg, float* __restrict__ zin, int Nnodes)
{
    const int lane = threadIdx.x & 31;
    const int warp = (blockIdx.x * blockDim.x + threadIdx.x) >> 5;
    const int nwarps = (gridDim.x * blockDim.x) >> 5;

    float4 w[8];
#pragma unroll
    for (int k = 0; k < 8; k++)
        w[k] = __ldg(reinterpret_cast<const float4*>(We + k * DD + lane * 4));
    const float4 bb = __ldg(reinterpret_cast<const float4*>(be + lane * 4));

    for (int d = warp; d < Nnodes; d += nwarps) {
        const int o0 = __ldg(start + d);
        const int o1 = o0 + __ldg(deg + d);
        float4 acc = *reinterpret_cast<const float4*>(hin + (size_t)d * DD + lane * 4);
        int j = o0;
        for (; j + 2 <= o1; j += 2) {
            const int s0 = __ldg(srcs + j);
            const int s1 = __ldg(srcs + j + 1);
            const float4 hv0 = __ldg(reinterpret_cast<const float4*>(hin + (size_t)s0 * DD + lane * 4));
            const float4 hv1 = __ldg(reinterpret_cast<const float4*>(hin + (size_t)s1 * DD + lane * 4));
            const float4 a00 = __ldg(reinterpret_cast<const float4*>(easort + (size_t)j * 8));
            const float4 a01 = __ldg(reinterpret_cast<const float4*>(easort + (size_t)j * 8 + 4));
            const float4 a10 = __ldg(reinterpret_cast<const float4*>(easort + (size_t)(j + 1) * 8));
            const float4 a11 = __ldg(reinterpret_cast<const float4*>(easort + (size_t)(j + 1) * 8 + 4));
            const float k0[8] = {a00.x, a00.y, a00.z, a00.w, a01.x, a01.y, a01.z, a01.w};
            const float k1[8] = {a10.x, a10.y, a10.z, a10.w, a11.x, a11.y, a11.z, a11.w};
            float4 e0 = bb, e1 = bb;
#pragma unroll
            for (int k = 0; k < 8; k++) {
                e0.x = fmaf(k0[k], w[k].x, e0.x);
                e0.y = fmaf(k0[k], w[k].y, e0.y);
                e0.z = fmaf(k0[k], w[k].z, e0.z);
                e0.w = fmaf(k0[k], w[k].w, e0.w);
                e1.x = fmaf(k1[k], w[k].x, e1.x);
                e1.y = fmaf(k1[k], w[k].y, e1.y);
                e1.z = fmaf(k1[k], w[k].z, e1.z);
                e1.w = fmaf(k1[k], w[k].w, e1.w);
            }
            acc.x += fmaxf(hv0.x + e0.x, 0.f) + fmaxf(hv1.x + e1.x, 0.f);
            acc.y += fmaxf(hv0.y + e0.y, 0.f) + fmaxf(hv1.y + e1.y, 0.f);
            acc.z += fmaxf(hv0.z + e0.z, 0.f) + fmaxf(hv1.z + e1.z, 0.f);
            acc.w += fmaxf(hv0.w + e0.w, 0.f) + fmaxf(hv1.w + e1.w, 0.f);
        }
        if (j < o1) {
            const int s = __ldg(srcs + j);
            const float4 hv = __ldg(reinterpret_cast<const float4*>(hin + (size_t)s * DD + lane * 4));
            const float4 a0 = __ldg(reinterpret_cast<const float4*>(easort + (size_t)j * 8));
            const float4 a1 = __ldg(reinterpret_cast<const float4*>(easort + (size_t)j * 8 + 4));
            const float ak[8] = {a0.x, a0.y, a0.z, a0.w, a1.x, a1.y, a1.z, a1.w};
            float4 e = bb;
#pragma unroll
            for (int k = 0; k < 8; k++) {
                e.x = fmaf(ak[k], w[k].x, e.x);
                e.y = fmaf(ak[k], w[k].y, e.y);
                e.z = fmaf(ak[k], w[k].z, e.z);
                e.w = fmaf(ak[k], w[k].w, e.w);
            }
            acc.x += fmaxf(hv.x + e.x, 0.f);
            acc.y += fmaxf(hv.y + e.y, 0.f);
            acc.z += fmaxf(hv.z + e.z, 0.f);
            acc.w += fmaxf(hv.w + e.w, 0.f);
        }
        *reinterpret_cast<float4*>(zin + (size_t)d * DD + lane * 4) = acc;
    }
}

// ---------------- fragment prep kernels ---------------------------------------
// row-major input; MODE 0: v = A1 + A2 ; MODE 2: v = A1
template <int MODE>
__global__ void __launch_bounds__(256) prep_A(
    const float* __restrict__ A1, const float* __restrict__ A2,
    uint4* __restrict__ FH, uint4* __restrict__ FL, int M, int K, int total)
{
    int idx = blockIdx.x * 256 + threadIdx.x;
    if (idx >= total) return;
    const int lane = idx & 31;
    const int tile = idx >> 5;
    const int KT = K >> 4;
    const int mt = tile / KT;
    const int kt = tile - mt * KT;
    const int g = lane >> 2;
    const int c = kt * 16 + (lane & 3) * 2;
    const int r0 = mt * 16 + g;

    float2 v[4];
    const int rr[4] = {r0, r0 + 8, r0, r0 + 8};
    const int cc[4] = {c, c, c + 8, c + 8};
#pragma unroll
    for (int i = 0; i < 4; i++) {
        float2 a = make_float2(0.f, 0.f);
        if (rr[i] < M) {
            const size_t off = (size_t)rr[i] * K + cc[i];
            a = *reinterpret_cast<const float2*>(A1 + off);
            if (MODE == 0) {
                const float2 b = *reinterpret_cast<const float2*>(A2 + off);
                a.x += b.x; a.y += b.y;
            }
        }
        v[i] = a;
    }
    uint4 hi, lo;
    pack2_split(v[0].x, v[0].y, hi.x, lo.x);
    pack2_split(v[1].x, v[1].y, hi.y, lo.y);
    pack2_split(v[2].x, v[2].y, hi.z, lo.z);
    pack2_split(v[3].x, v[3].y, hi.w, lo.w);
    FH[tile * 32 + lane] = hi;
    FL[tile * 32 + lane] = lo;
}

// fragment-order input (z1f): apply relu(scale*z+shift), split to bf16 hi/lo.
__global__ void __launch_bounds__(256) prep_A_frag(
    const float4* __restrict__ Zf, const float* __restrict__ sc,
    const float* __restrict__ sh, uint4* __restrict__ FH, uint4* __restrict__ FL,
    int NT, int total)
{
    int idx = blockIdx.x * 256 + threadIdx.x;
    if (idx >= total) return;
    const int lane = idx & 31;
    const int tile = idx >> 5;
    const int KT = NT >> 1;
    const int mt = tile / KT;
    const int kt = tile - mt * KT;
    const int c0 = kt * 16 + (lane & 3) * 2;

    float4 v0 = __ldg(&Zf[((size_t)mt * NT + 2 * kt) * 32 + lane]);
    float4 v1 = __ldg(&Zf[((size_t)mt * NT + 2 * kt + 1) * 32 + lane]);
    const float2 s0 = *reinterpret_cast<const float2*>(sc + c0);
    const float2 t0 = *reinterpret_cast<const float2*>(sh + c0);
    const float2 s1 = *reinterpret_cast<const float2*>(sc + c0 + 8);
    const float2 t1 = *reinterpret_cast<const float2*>(sh + c0 + 8);
    v0.x = fmaxf(fmaf(s0.x, v0.x, t0.x), 0.f);
    v0.y = fmaxf(fmaf(s0.y, v0.y, t0.y), 0.f);
    v0.z = fmaxf(fmaf(s0.x, v0.z, t0.x), 0.f);
    v0.w = fmaxf(fmaf(s0.y, v0.w, t0.y), 0.f);
    v1.x = fmaxf(fmaf(s1.x, v1.x, t1.x), 0.f);
    v1.y = fmaxf(fmaf(s1.y, v1.y, t1.y), 0.f);
    v1.z = fmaxf(fmaf(s1.x, v1.z, t1.x), 0.f);
    v1.w = fmaxf(fmaf(s1.y, v1.w, t1.y), 0.f);

    uint4 hi, lo;
    pack2_split(v0.x, v0.y, hi.x, lo.x);
    pack2_split(v0.z, v0.w, hi.y, lo.y);
    pack2_split(v1.x, v1.y, hi.z, lo.z);
    pack2_split(v1.z, v1.w, hi.w, lo.w);
    FH[tile * 32 + lane] = hi;
    FL[tile * 32 + lane] = lo;
}

__global__ void __launch_bounds__(256) prep_W(
    const float* __restrict__ W, uint2* __restrict__ FH, uint2* __restrict__ FL,
    int F, int KT, int total)
{
    int idx = blockIdx.x * 256 + threadIdx.x;
    if (idx >= total) return;
    const int lane = idx & 31;
    const int tile = idx >> 5;
    const int nt = tile / KT;
    const int kt = tile - nt * KT;
    const int n = nt * 8 + (lane >> 2);
    const int k0 = kt * 16 + (lane & 3) * 2;
    const float p00 = __ldg(W + (size_t)k0 * F + n);
    const float p01 = __ldg(W + (size_t)(k0 + 1) * F + n);
    const float p10 = __ldg(W + (size_t)(k0 + 8) * F + n);
    const float p11 = __ldg(W + (size_t)(k0 + 9) * F + n);
    uint2 hi, lo;
    pack2_split(p00, p01, hi.x, lo.x);
    pack2_split(p10, p11, hi.y, lo.y);
    FH[tile * 32 + lane] = hi;
    FL[tile * 32 + lane] = lo;
}

// ---------------- fragment-direct tensor-core GEMM ----------------------------
// FRAGOUT=1: store C in fragment order (float4 per lane per m16n8 tile)
template <int FDIM, int FRAGOUT>
__global__ void __launch_bounds__(256) frag_gemm(
    const uint4* __restrict__ AH, const uint4* __restrict__ AL,
    const uint2* __restrict__ BH, const uint2* __restrict__ BL,
    const float* __restrict__ bias, float* __restrict__ C, int M, int KT)
{
    const int lane = threadIdx.x & 31;
    const int wid = threadIdx.x >> 5;
    const int warp_m = wid & 3;
    const int warp_n = wid >> 2;
    const int mt0 = blockIdx.y * 8 + warp_m * 2;
    const int nt0 = blockIdx.x * 16 + warp_n * 8;

    float acc[2][8][4];
#pragma unroll
    for (int i = 0; i < 2; i++)
#pragma unroll
        for (int j = 0; j < 8; j++)
#pragma unroll
            for (int q = 0; q < 4; q++) acc[i][j][q] = 0.f;

    for (int kt = 0; kt < KT; kt++) {
        uint4 ah[2], al[2];
#pragma unroll
        for (int im = 0; im < 2; im++) {
            const size_t aidx = ((size_t)(mt0 + im) * KT + kt) * 32 + lane;
            ah[im] = __ldg(&AH[aidx]);
            al[im] = __ldg(&AL[aidx]);
        }
        uint2 bh[8], bl[8];
#pragma unroll
        for (int nb = 0; nb < 8; nb++) {
            const size_t bidx = ((size_t)(nt0 + nb) * KT + kt) * 32 + lane;
            bh[nb] = __ldg(&BH[bidx]);
            bl[nb] = __ldg(&BL[bidx]);
        }
#pragma unroll
        for (int im = 0; im < 2; im++)
#pragma unroll
            for (int nb = 0; nb < 8; nb++) {
                mma_bf16_v(acc[im][nb], reinterpret_cast<const uint32_t*>(&ah[im]),
                           reinterpret_cast<const uint32_t*>(&bh[nb]));
                mma_bf16_v(acc[im][nb], reinterpret_cast<const uint32_t*>(&ah[im]),
                           reinterpret_cast<const uint32_t*>(&bl[nb]));
                mma_bf16_v(acc[im][nb], reinterpret_cast<const uint32_t*>(&al[im]),
                           reinterpret_cast<const uint32_t*>(&bh[nb]));
            }
    }

    const int gid = lane >> 2;
    const int tig = lane & 3;
    if (FRAGOUT) {
        const int NT = FDIM / 8;
#pragma unroll
        for (int im = 0; im < 2; im++) {
            const int mt = mt0 + im;
#pragma unroll
            for (int nb = 0; nb < 8; nb++) {
                const int ntg = nt0 + nb;
                const int col = ntg * 8 + tig * 2;
                const float2 bv = *reinterpret_cast<const float2*>(bias + col);
                float4 o = make_float4(acc[im][nb][0] + bv.x, acc[im][nb][1] + bv.y,
                                       acc[im][nb][2] + bv.x, acc[im][nb][3] + bv.y);
                *reinterpret_cast<float4*>(C + (((size_t)mt * NT + ntg) * 32 + lane) * 4) = o;
            }
        }
    } else {
#pragma unroll
        for (int im = 0; im < 2; im++) {
            const int rbase = blockIdx.y * 128 + warp_m * 32 + im * 16;
            const int r0 = rbase + gid;
            const int r1 = r0 + 8;
#pragma unroll
            for (int nb = 0; nb < 8; nb++) {
                const int col = blockIdx.x * 128 + warp_n * 64 + nb * 8 + tig * 2;
                const float2 bv = *reinterpret_cast<const float2*>(bias + col);
                if (r0 < M) {
                    float2 o = make_float2(acc[im][nb][0] + bv.x, acc[im][nb][1] + bv.y);
                    *reinterpret_cast<float2*>(C + (size_t)r0 * FDIM + col) = o;
                }
                if (r1 < M) {
                    float2 o = make_float2(acc[im][nb][2] + bv.x, acc[im][nb][3] + bv.y);
                    *reinterpret_cast<float2*>(C + (size_t)r1 * FDIM + col) = o;
                }
            }
        }
    }
}

// ---------------- stats over fragment-order buffer -----------------------------
__global__ void __launch_bounds__(256) stats_frag_kernel(
    const float4* __restrict__ Zf, int M, int NT,
    float* __restrict__ gsum, float* __restrict__ gsq)
{
    const int nb = blockIdx.x;
    const int lane = threadIdx.x & 31;
    const int w = threadIdx.x >> 5;          // 8 warps
    const int tig = lane & 3;
    const int g = lane >> 2;
    const int mtfull = M >> 4;
    const int rem = M & 15;
    float s0 = 0.f, s1 = 0.f, q0 = 0.f, q1 = 0.f;
    for (int mt = blockIdx.y * 8 + w; mt < mtfull; mt += gridDim.y * 8) {
        const float4 v = __ldg(&Zf[((size_t)mt * NT + nb) * 32 + lane]);
        s0 += v.x + v.z; q0 = fmaf(v.x, v.x, fmaf(v.z, v.z, q0));
        s1 += v.y + v.w; q1 = fmaf(v.y, v.y, fmaf(v.w, v.w, q1));
    }
    if (rem && blockIdx.y == 0 && w == 0) {
        const float4 v = __ldg(&Zf[((size_t)mtfull * NT + nb) * 32 + lane]);
        if (g < rem)     { s0 += v.x; q0 = fmaf(v.x, v.x, q0); s1 += v.y; q1 = fmaf(v.y, v.y, q1); }
        if (g + 8 < rem) { s0 += v.z; q0 = fmaf(v.z, v.z, q0); s1 += v.w; q1 = fmaf(v.w, v.w, q1); }
    }
#pragma unroll
    for (int off = 4; off < 32; off <<= 1) {
        s0 += __shfl_xor_sync(0xffffffffu, s0, off);
        s1 += __shfl_xor_sync(0xffffffffu, s1, off);
        q0 += __shfl_xor_sync(0xffffffffu, q0, off);
        q1 += __shfl_xor_sync(0xffffffffu, q1, off);
    }
    __shared__ float sm[8][4][4];
    if (lane < 4) {
        sm[w][tig][0] = s0; sm[w][tig][1] = s1;
        sm[w][tig][2] = q0; sm[w][tig][3] = q1;
    }
    __syncthreads();
    if (threadIdx.x < 4) {
        const int t = threadIdx.x;
        float S0 = 0.f, S1 = 0.f, Q0 = 0.f, Q1 = 0.f;
#pragma unroll
        for (int ww = 0; ww < 8; ww++) {
            S0 += sm[ww][t][0]; S1 += sm[ww][t][1];
            Q0 += sm[ww][t][2]; Q1 += sm[ww][t][3];
        }
        const int col = nb * 8 + t * 2;
        atomicAdd(&gsum[col], S0);
        atomicAdd(&gsum[col + 1], S1);
        atomicAdd(&gsq[col], Q0);
        atomicAdd(&gsq[col + 1], Q1);
    }
}

// ---------------- elementwise / misc kernels ----------------------------------
// one-time init: vn broadcast, stats accumulators, AND pooled=0 (for layer 0)
__global__ void init_vn_kernel(const float* __restrict__ vn_emb, float* __restrict__ vn,
                               float* __restrict__ s, float* __restrict__ q,
                               float* __restrict__ pooled) {
    int idx = blockIdx.x * blockDim.x + threadIdx.x;
    if (idx < GG * DD) {
        vn[idx] = vn_emb[idx & (DD - 1)];
        pooled[idx] = 0.f;
    }
    if (idx < HH) { s[idx] = 0.f; q[idx] = 0.f; }
}

// h_in = op(A) + vn[batch];  POOL: pooled[batch] += h_in
template <int MODE, int POOL>
__global__ void hin_kernel(const float* __restrict__ A,
                           const float* __restrict__ sc, const float* __restrict__ sh,
                           const float* __restrict__ vn, const int* __restrict__ batch,
                           float* __restrict__ hin, float* __restrict__ pooled, int n) {
    int idx = blockIdx.x * blockDim.x + threadIdx.x;
    int total = n * (DD / 4);
    if (idx >= total) return;
    int row = idx >> 5;
    int c4 = (idx & 31) << 2;
    int g = batch[row];
    float4 a = *reinterpret_cast<const float4*>(A + (size_t)row * DD + c4);
    if (MODE == 1) {
        const float4 s = __ldg(reinterpret_cast<const float4*>(sc + c4));
        const float4 t = __ldg(reinterpret_cast<const float4*>(sh + c4));
        a.x = fmaxf(fmaf(s.x, a.x, t.x), 0.f);
        a.y = fmaxf(fmaf(s.y, a.y, t.y), 0.f);
        a.z = fmaxf(fmaf(s.z, a.z, t.z), 0.f);
        a.w = fmaxf(fmaf(s.w, a.w, t.w), 0.f);
    }
    const float4 b = *reinterpret_cast<const float4*>(vn + (size_t)g * DD + c4);
    float4 o = make_float4(a.x + b.x, a.y + b.y, a.z + b.z, a.w + b.w);
    *reinterpret_cast<float4*>(hin + (size_t)row * DD + c4) = o;
    if (POOL) atomic_add_f4(pooled + (size_t)g * DD + c4, o);
}

// SIMT GEMM for the tiny virtual-node MLPs (512 rows)
template <int MODE>
__global__ void __launch_bounds__(256) gemm_kernel(
    const float* __restrict__ A1, const float* __restrict__ A2,
    const float* __restrict__ bnscale, const float* __restrict__ bnshift,
    const float* __restrict__ B, const float* __restrict__ bias,
    float* __restrict__ C, int M, int K, int F)
{
    const int BM = 128, BN = 128, BK = 16;
    __shared__ float sA[BK][BM];
    __shared__ float sB[BK][BN];
    int tid = threadIdx.x;
    int brow = blockIdx.y * BM;
    int bcol = blockIdx.x * BN;

    float acc[8][8];
#pragma unroll
    for (int i = 0; i < 8; i++)
#pragma unroll
        for (int j = 0; j < 8; j++) acc[i][j] = 0.f;

    int tr = (tid >> 4) << 3;
    int tc = (tid & 15) << 3;

    for (int k0 = 0; k0 < K; k0 += BK) {
#pragma unroll
        for (int i = 0; i < 2; i++) {
            int idx = tid + i * 256;
            int r = idx >> 2;
            int c4 = (idx & 3) << 2;
            int row = brow + r;
            float4 v = make_float4(0.f, 0.f, 0.f, 0.f);
            if (row < M) {
                size_t off = (size_t)row * K + k0 + c4;
                if (MODE == 0) {
                    float4 a = __ldg(reinterpret_cast<const float4*>(A1 + off));
                    float4 b = __ldg(reinterpret_cast<const float4*>(A2 + off));
                    v = make_float4(a.x + b.x, a.y + b.y, a.z + b.z, a.w + b.w);
                } else {
                    float4 a = __ldg(reinterpret_cast<const float4*>(A1 + off));
                    float4 s = __ldg(reinterpret_cast<const float4*>(bnscale + k0 + c4));
                    float4 t = __ldg(reinterpret_cast<const float4*>(bnshift + k0 + c4));
                    v.x = fmaxf(fmaf(s.x, a.x, t.x), 0.f);
                    v.y = fmaxf(fmaf(s.y, a.y, t.y), 0.f);
                    v.z = fmaxf(fmaf(s.z, a.z, t.z), 0.f);
                    v.w = fmaxf(fmaf(s.w, a.w, t.w), 0.f);
                }
            }
            sA[c4 + 0][r] = v.x;
            sA[c4 + 1][r] = v.y;
            sA[c4 + 2][r] = v.z;
            sA[c4 + 3][r] = v.w;
        }
#pragma unroll
        for (int i = 0; i < 2; i++) {
            int idx = tid + i * 256;
            int r = idx >> 5;
            int c4 = (idx & 31) << 2;
            float4 v = __ldg(reinterpret_cast<const float4*>(B + (size_t)(k0 + r) * F + bcol + c4));
            *reinterpret_cast<float4*>(&sB[r][c4]) = v;
        }
        __syncthreads();
#pragma unroll
        for (int kk = 0; kk < BK; kk++) {
            float a[8], b[8];
            *reinterpret_cast<float4*>(&a[0]) = *reinterpret_cast<float4*>(&sA[kk][tr]);
            *reinterpret_cast<float4*>(&a[4]) = *reinterpret_cast<float4*>(&sA[kk][tr + 4]);
            *reinterpret_cast<float4*>(&b[0]) = *reinterpret_cast<float4*>(&sB[kk][tc]);
            *reinterpret_cast<float4*>(&b[4]) = *reinterpret_cast<float4*>(&sB[kk][tc + 4]);
#pragma unroll
            for (int i = 0; i < 8; i++)
#pragma unroll
                for (int j = 0; j < 8; j++)
                    acc[i][j] = fmaf(a[i], b[j], acc[i][j]);
        }
        __syncthreads();
    }
#pragma unroll
    for (int i = 0; i < 8; i++) {
        int row = brow + tr + i;
        if (row < M) {
#pragma unroll
            for (int j = 0; j < 8; j += 4) {
                float4 bv = __ldg(reinterpret_cast<const float4*>(bias + bcol + tc + j));
                float4 o;
                o.x = acc[i][j + 0] + bv.x;
                o.y = acc[i][j + 1] + bv.y;
                o.z = acc[i][j + 2] + bv.z;
                o.w = acc[i][j + 3] + bv.w;
                *reinterpret_cast<float4*>(C + (size_t)row * F + bcol + tc + j) = o;
            }
        }
    }
}

__global__ void stats_kernel(const float* __restrict__ Z, int M, int F,
                             float* __restrict__ gsum, float* __restrict__ gsq) {
    int col = threadIdx.x;
    int r0 = blockIdx.x * 128;
    int rend = min(r0 + 128, M);
    float s = 0.f, q = 0.f;
    for (int r = r0; r < rend; r++) {
        float v = Z[(size_t)r * F + col];
        s += v;
        q = fmaf(v, v, q);
    }
    atomicAdd(&gsum[col], s);
    atomicAdd(&gsq[col], q);
}

// consume stats, produce scale/shift, then zero the accumulators for reuse
__global__ void bn_finalize_kernel(float* __restrict__ gsum, float* __restrict__ gsq,
                                   const float* __restrict__ gamma, const float* __restrict__ beta,
                                   int M, float* __restrict__ scale, float* __restrict__ shift) {
    int f = threadIdx.x;
    float invM = 1.f / (float)M;
    float mean = gsum[f] * invM;
    float var = gsq[f] * invM - mean * mean;
    float inv = rsqrtf(var + BN_EPS);
    float sc = gamma[f] * inv;
    scale[f] = sc;
    shift[f] = beta[f] - mean * sc;
    gsum[f] = 0.f;
    gsq[f] = 0.f;
}

__global__ void bn_apply_kernel(const float* __restrict__ Z, const float* __restrict__ scale,
                                const float* __restrict__ shift, float* __restrict__ out,
                                int M, int F, int do_relu) {
    int idx = blockIdx.x * blockDim.x + threadIdx.x;
    int total = M * (F >> 2);
    if (idx >= total) return;
    int cols4 = F >> 2;
    int row = idx / cols4;
    int c4 = (idx - row * cols4) << 2;
    float4 z = *reinterpret_cast<const float4*>(Z + (size_t)row * F + c4);
    float4 s = __ldg(reinterpret_cast<const float4*>(scale + c4));
    float4 t = __ldg(reinterpret_cast<const float4*>(shift + c4));
    float4 o;
    o.x = fmaf(s.x, z.x, t.x);
    o.y = fmaf(s.y, z.y, t.y);
    o.z = fmaf(s.z, z.z, t.z);
    o.w = fmaf(s.w, z.w, t.w);
    if (do_relu) {
        o.x = fmaxf(o.x, 0.f);
        o.y = fmaxf(o.y, 0.f);
        o.z = fmaxf(o.z, 0.f);
        o.w = fmaxf(o.w, 0.f);
    }
    *reinterpret_cast<float4*>(out + (size_t)row * F + c4) = o;
}

// vn = relu(scale*Z + shift)  AND  pooled = 0 (prepares next layer's pooling)
__global__ void bn_apply_vn_kernel(const float* __restrict__ Z, const float* __restrict__ scale,
                                   const float* __restrict__ shift, float* __restrict__ vn,
                                   float* __restrict__ pooled) {
    int idx = blockIdx.x * blockDim.x + threadIdx.x;
    int total = GG * (DD >> 2);
    if (idx >= total) return;
    int row = idx >> 5;
    int c4 = (idx & 31) << 2;
    float4 z = *reinterpret_cast<const float4*>(Z + (size_t)row * DD + c4);
    float4 s = __ldg(reinterpret_cast<const float4*>(scale + c4));
    float4 t = __ldg(reinterpret_cast<const float4*>(shift + c4));
    float4 o;
    o.x = fmaxf(fmaf(s.x, z.x, t.x), 0.f);
    o.y = fmaxf(fmaf(s.y, z.y, t.y), 0.f);
    o.z = fmaxf(fmaf(s.z, z.z, t.z), 0.f);
    o.w = fmaxf(fmaf(s.w, z.w, t.w), 0.f);
    *reinterpret_cast<float4*>(vn + (size_t)row * DD + c4) = o;
    *reinterpret_cast<float4*>(pooled + (size_t)row * DD + c4) = make_float4(0.f, 0.f, 0.f, 0.f);
}

// ------------------------------ host driver ----------------------------------
static inline int cdiv(int a, int b) { return (a + b - 1) / b; }

extern "C" void kernel_launch(void* const* d_in, const int* in_sizes, int n_in,
                              void* d_out, int out_size) {
    const float* x        = (const float*)d_in[0];
    const float* edge_attr= (const float*)d_in[1];
    const float* vn_emb   = (const float*)d_in[2];
    const float* We   = (const float*)d_in[3];
    const float* be   = (const float*)d_in[4];
    const float* W1   = (const float*)d_in[5];
    const float* b1   = (const float*)d_in[6];
    const float* g1   = (const float*)d_in[7];
    const float* bt1  = (const float*)d_in[8];
    const float* W2   = (const float*)d_in[9];
    const float* b2   = (const float*)d_in[10];
    const float* gb   = (const float*)d_in[11];
    const float* bbp  = (const float*)d_in[12];
    const float* Wv1  = (const float*)d_in[13];
    const float* bv1  = (const float*)d_in[14];
    const float* gv1  = (const float*)d_in[15];
    const float* btv1 = (const float*)d_in[16];
    const float* Wv2  = (const float*)d_in[17];
    const float* bv2  = (const float*)d_in[18];
    const float* gv2  = (const float*)d_in[19];
    const float* btv2 = (const float*)d_in[20];
    const int* edge_index = (const int*)d_in[21];
    const int* batch      = (const int*)d_in[22];

    const int N = in_sizes[0] / DD;
    const int E = in_sizes[1] / 8;
    const int* srcp = edge_index;
    const int* dstp = edge_index + E;
    float* out = (float*)d_out;

    float *p_hin, *p_zin, *p_z1f, *p_z2, *p_vn, *p_pooled, *p_tv1, *p_tv2;
    float *p_sum, *p_sq, *p_scale, *p_shift, *p_scale2, *p_shift2, *p_easort;
    int *p_deg, *p_start, *p_cursor, *p_counter, *p_srcs;
    uint4 *p_fAH, *p_fAL;
    uint2 *p_fWH, *p_fWL;
    cudaGetSymbolAddress((void**)&p_hin, g_hin);
    cudaGetSymbolAddress((void**)&p_zin, g_zin);
    cudaGetSymbolAddress((void**)&p_z1f, g_z1f);
    cudaGetSymbolAddress((void**)&p_z2, g_z2);
    cudaGetSymbolAddress((void**)&p_vn, g_vn);
    cudaGetSymbolAddress((void**)&p_pooled, g_pooled);
    cudaGetSymbolAddress((void**)&p_tv1, g_tv1);
    cudaGetSymbolAddress((void**)&p_tv2, g_tv2);
    cudaGetSymbolAddress((void**)&p_sum, g_sum);
    cudaGetSymbolAddress((void**)&p_sq, g_sumsq);
    cudaGetSymbolAddress((void**)&p_scale, g_scale);
    cudaGetSymbolAddress((void**)&p_shift, g_shift);
    cudaGetSymbolAddress((void**)&p_scale2, g_scale2);
    cudaGetSymbolAddress((void**)&p_shift2, g_shift2);
    cudaGetSymbolAddress((void**)&p_easort, g_easort);
    cudaGetSymbolAddress((void**)&p_deg, g_deg);
    cudaGetSymbolAddress((void**)&p_start, g_start);
    cudaGetSymbolAddress((void**)&p_cursor, g_cursor);
    cudaGetSymbolAddress((void**)&p_counter, g_counter);
    cudaGetSymbolAddress((void**)&p_srcs, g_srcs);
    cudaGetSymbolAddress((void**)&p_fAH, g_fAH);
    cudaGetSymbolAddress((void**)&p_fAL, g_fAL);
    cudaGetSymbolAddress((void**)&p_fWH, g_fWH);
    cudaGetSymbolAddress((void**)&p_fWL, g_fWL);

    // ---- one-time per call: init vn + stats + pooled=0 + CSR build ----
    init_vn_kernel<<<cdiv(GG * DD, 256), 256>>>(vn_emb, p_vn, p_sum, p_sq, p_pooled);
    zero_deg_kernel<<<cdiv(N, 256), 256>>>(p_deg, p_counter, N);
    hist_kernel<<<cdiv(E, 256), 256>>>(dstp, p_deg, E);
    alloc_kernel<<<cdiv(N, 256), 256>>>(p_deg, p_start, p_cursor, p_counter, N);
    scatter_kernel<<<cdiv(E, 256), 256>>>(srcp, dstp, edge_attr, p_cursor,
                                          p_srcs, p_easort, E);

    const int nf4 = N * (DD / 4);

    for (int l = 0; l < LL; l++) {
        const int need_pool = (l < LL - 1);
        // h_in = op(prev) + vn[batch]; pooled[batch] += h_in
        // (pooled pre-zeroed: by init_vn for l=0, by bn_apply_vn of layer l-1 otherwise)
        if (l == 0) {
            if (need_pool)
                hin_kernel<0, 1><<<cdiv(nf4, 256), 256>>>(x, nullptr, nullptr, p_vn, batch,
                                                          p_hin, p_pooled, N);
            else
                hin_kernel<0, 0><<<cdiv(nf4, 256), 256>>>(x, nullptr, nullptr, p_vn, batch,
                                                          p_hin, p_pooled, N);
        } else {
            if (need_pool)
                hin_kernel<1, 1><<<cdiv(nf4, 256), 256>>>(p_z2, p_scale2, p_shift2, p_vn, batch,
                                                          p_hin, p_pooled, N);
            else
                hin_kernel<1, 0><<<cdiv(nf4, 256), 256>>>(p_z2, p_scale2, p_shift2, p_vn, batch,
                                                          p_hin, p_pooled, N);
        }
        // zin = h_in + sum_edges relu(h_in[src] + MLP(ea))   (atomic-free CSR)
        edge_aggr_kernel<<<2048, 256>>>(p_easort, We + (size_t)l * 8 * DD,
                                        be + (size_t)l * DD, p_hin, p_srcs, p_start,
                                        p_deg, p_zin, N);

        // ---- z1f = zin @ W1 + b1  (fragment-order output)  [N x HH], K=DD ----
        {
            const int KT = DD / 16;
            const int wtot = (HH / 8) * KT * 32;
            prep_W<<<cdiv(wtot, 256), 256>>>(W1 + (size_t)l * DD * HH, p_fWH, p_fWL, HH, KT, wtot);
            const int atot = MT_TILES * KT * 32;
            prep_A<2><<<cdiv(atot, 256), 256>>>(p_zin, nullptr, p_fAH, p_fAL, N, DD, atot);
            dim3 grid(HH / 128, GRID_ROWS);
            frag_gemm<HH, 1><<<grid, 256>>>(p_fAH, p_fAL, p_fWH, p_fWL,
                                            b1 + (size_t)l * HH, p_z1f, N, KT);
        }
        {
            dim3 sgrid(HH / 8, 8);
            stats_frag_kernel<<<sgrid, 256>>>((const float4*)p_z1f, N, HH / 8, p_sum, p_sq);
        }
        bn_finalize_kernel<<<1, HH>>>(p_sum, p_sq, g1 + (size_t)l * HH, bt1 + (size_t)l * HH,
                                      N, p_scale, p_shift);

        // ---- z2 = relu(BN(z1)) @ W2 + b2    [N x DD], K=HH ----
        {
            const int KT = HH / 16;
            const int wtot = (DD / 8) * KT * 32;
            prep_W<<<cdiv(wtot, 256), 256>>>(W2 + (size_t)l * HH * DD, p_fWH, p_fWL, DD, KT, wtot);
            const int atot = MT_TILES * KT * 32;
            prep_A_frag<<<cdiv(atot, 256), 256>>>((const float4*)p_z1f, p_scale, p_shift,
                                                  p_fAH, p_fAL, HH / 8, atot);
            dim3 grid(DD / 128, GRID_ROWS);
            frag_gemm<DD, 0><<<grid, 256>>>(p_fAH, p_fAL, p_fWH, p_fWL,
                                            b2 + (size_t)l * DD, p_z2, N, KT);
        }
        stats_kernel<<<cdiv(N, 128), DD>>>(p_z2, N, DD, p_sum, p_sq);
        bn_finalize_kernel<<<1, DD>>>(p_sum, p_sq, gb + (size_t)l * DD, bbp + (size_t)l * DD,
                                      N, p_scale2, p_shift2);

        if (l < LL - 1) {
            // ---- virtual node update (tiny, SIMT path) ----
            {
                dim3 grid(HH / 128, cdiv(GG, 128));
                gemm_kernel<0><<<grid, 256>>>(p_pooled, p_vn, nullptr, nullptr,
                                              Wv1 + (size_t)l * DD * HH, bv1 + (size_t)l * HH,
                                              p_tv1, GG, DD, HH);
            }
            stats_kernel<<<cdiv(GG, 128), HH>>>(p_tv1, GG, HH, p_sum, p_sq);
            bn_finalize_kernel<<<1, HH>>>(p_sum, p_sq, gv1 + (size_t)l * HH, btv1 + (size_t)l * HH,
                                          GG, p_scale, p_shift);
            {
                dim3 grid(DD / 128, cdiv(GG, 128));
                gemm_kernel<1><<<grid, 256>>>(p_tv1, nullptr, p_scale, p_shift,
                                              Wv2 + (size_t)l * HH * DD, bv2 + (size_t)l * DD,
                                              p_tv2, GG, HH, DD);
            }
            stats_kernel<<<cdiv(GG, 128), DD>>>(p_tv2, GG, DD, p_sum, p_sq);
            bn_finalize_kernel<<<1, DD>>>(p_sum, p_sq, gv2 + (size_t)l * DD, btv2 + (size_t)l * DD,
                                          GG, p_scale, p_shift);
            // vn = relu(BN(tv2)); also re-zero pooled for the next layer's pooling
            bn_apply_vn_kernel<<<cdiv(GG * DD / 4, 256), 256>>>(p_tv2, p_scale, p_shift,
                                                                p_vn, p_pooled);
        } else {
            bn_apply_kernel<<<cdiv(nf4, 256), 256>>>(p_z2, p_scale2, p_shift2, out, N, DD, 0);
        }
    }
}

// round 16
// speedup vs baseline: 1.1489x; 1.0299x over previous
#include <cuda_runtime.h>
#include <cuda_bf16.h>
#include <cstdint>

#define NN 50000
#define EE 800000
#define DD 128
#define HH 256
#define GG 512
#define LL 3
#define BN_EPS 1e-5f

#define MPAD 50048                 // NN rounded up to multiple of 128
#define MT_TILES (MPAD / 16)       // 3128 m16 tiles
#define GRID_ROWS (MPAD / 128)     // 391

// ---------------- scratch (static device globals; no allocation) -------------
__device__ float g_hin[NN * DD];
__device__ float g_zin[NN * DD];
__device__ float g_z1f[MPAD * HH];   // z1 in fragment order (fp32)
__device__ float g_z2[NN * DD];
__device__ float g_vn[GG * DD];
__device__ float g_pooled[GG * DD];
__device__ float g_tv1[GG * HH];
__device__ float g_tv2[GG * DD];
__device__ float g_sum[HH];
__device__ float g_sumsq[HH];
__device__ float g_scale[HH];
__device__ float g_shift[HH];
__device__ float g_scale2[DD];
__device__ float g_shift2[DD];

// CSR (built once per launch; graph constant across layers)
__device__ int g_deg[NN];
__device__ int g_start[NN];
__device__ int g_cursor[NN];
__device__ int g_counter;
__device__ int g_srcs[EE];
__device__ float g_easort[EE * 8];

// fragment-order bf16 scratch
__device__ uint4 g_fAH[MPAD * 256 / 8];
__device__ uint4 g_fAL[MPAD * 256 / 8];
__device__ uint2 g_fWH[16384];
__device__ uint2 g_fWL[16384];

// ---------------- helpers ----------------------------------------------------
__device__ __forceinline__ void atomic_add_f4(float* addr, float4 v) {
    asm volatile("red.global.add.v4.f32 [%0], {%1,%2,%3,%4};"
                 :: "l"(addr), "f"(v.x), "f"(v.y), "f"(v.z), "f"(v.w)
                 : "memory");
}

__device__ __forceinline__ void pack2_split(float x, float y, uint32_t& h, uint32_t& l) {
    __nv_bfloat162 hb = __floats2bfloat162_rn(x, y);
    float rx = x - __bfloat162float(hb.x);
    float ry = y - __bfloat162float(hb.y);
    __nv_bfloat162 lb = __floats2bfloat162_rn(rx, ry);
    h = *reinterpret_cast<uint32_t*>(&hb);
    l = *reinterpret_cast<uint32_t*>(&lb);
}

__device__ __forceinline__ void mma_bf16_v(float* d, const uint32_t* a, const uint32_t* b) {
    asm volatile(
        "mma.sync.aligned.m16n8k16.row.col.f32.bf16.bf16.f32 "
        "{%0,%1,%2,%3}, {%4,%5,%6,%7}, {%8,%9}, {%0,%1,%2,%3};"
        : "+f"(d[0]), "+f"(d[1]), "+f"(d[2]), "+f"(d[3])
        : "r"(a[0]), "r"(a[1]), "r"(a[2]), "r"(a[3]), "r"(b[0]), "r"(b[1]));
}

// ---------------- CSR build ----------------------------------------------------
__global__ void zero_deg_kernel(int* __restrict__ deg, int* __restrict__ counter, int n) {
    int i = blockIdx.x * blockDim.x + threadIdx.x;
    if (i < n) deg[i] = 0;
    if (i == 0) *counter = 0;
}

__global__ void hist_kernel(const int* __restrict__ dst, int* __restrict__ deg, int E) {
    int e = blockIdx.x * blockDim.x + threadIdx.x;
    if (e < E) atomicAdd(&deg[dst[e]], 1);
}

// per-block shared scan + one atomicAdd per block (segments non-monotonic, fine)
__global__ void __launch_bounds__(256) alloc_kernel(
    const int* __restrict__ deg, int* __restrict__ start, int* __restrict__ cursor,
    int* __restrict__ counter, int n)
{
    __shared__ int sh[256];
    __shared__ int sbase;
    const int t = threadIdx.x;
    const int i = blockIdx.x * 256 + t;
    const int d = (i < n) ? __ldg(deg + i) : 0;
    sh[t] = d;
    __syncthreads();
#pragma unroll
    for (int o = 1; o < 256; o <<= 1) {
        int v = (t >= o) ? sh[t - o] : 0;
        __syncthreads();
        sh[t] += v;
        __syncthreads();
    }
    if (t == 255) sbase = atomicAdd(counter, sh[255]);
    __syncthreads();
    if (i < n) {
        const int s = sbase + sh[t] - d;
        start[i] = s;
        cursor[i] = s;
    }
}

__global__ void scatter_kernel(const int* __restrict__ src, const int* __restrict__ dst,
                               const float* __restrict__ ea, int* __restrict__ cursor,
                               int* __restrict__ srcs, float* __restrict__ easort, int E)
{
    int e = blockIdx.x * blockDim.x + threadIdx.x;
    if (e >= E) return;
    const int d = dst[e];
    const int pos = atomicAdd(&cursor[d], 1);
    srcs[pos] = src[e];
    const float4 a0 = __ldg(reinterpret_cast<const float4*>(ea + (size_t)e * 8));
    const float4 a1 = __ldg(reinterpret_cast<const float4*>(ea + (size_t)e * 8 + 4));
    *reinterpret_cast<float4*>(easort + (size_t)pos * 8) = a0;
    *reinterpret_cast<float4*>(easort + (size_t)pos * 8 + 4) = a1;
}

// ---------------- CSR edge aggregation (atomic-free, unroll-2, reg weights) ---
// warp per dst node: zin[d] = hin[d] + sum_j relu(hin[src_j] + MLP(ea_j))
__global__ void __launch_bounds__(256) edge_aggr_kernel(
    const float* __restrict__ easort, const float* __restrict__ We,
    const float* __restrict__ be, const float* __restrict__ hin,
    const int* __restrict__ srcs, const int* __restrict__ start,
    const int* __restrict__ deg, float* __restrict__ zin, int Nnodes)
{
    const int lane = threadIdx.x & 31;
    const int warp = (blockIdx.x * blockDim.x + threadIdx.x) >> 5;
    const int nwarps = (gridDim.x * blockDim.x) >> 5;

    float4 w[8];
#pragma unroll
    for (int k = 0; k < 8; k++)
        w[k] = __ldg(reinterpret_cast<const float4*>(We + k * DD + lane * 4));
    const float4 bb = __ldg(reinterpret_cast<const float4*>(be + lane * 4));

    for (int d = warp; d < Nnodes; d += nwarps) {
        const int o0 = __ldg(start + d);
        const int o1 = o0 + __ldg(deg + d);
        float4 acc = *reinterpret_cast<const float4*>(hin + (size_t)d * DD + lane * 4);
        int j = o0;
        for (; j + 2 <= o1; j += 2) {
            const int s0 = __ldg(srcs + j);
            const int s1 = __ldg(srcs + j + 1);
            const float4 hv0 = __ldg(reinterpret_cast<const float4*>(hin + (size_t)s0 * DD + lane * 4));
            const float4 hv1 = __ldg(reinterpret_cast<const float4*>(hin + (size_t)s1 * DD + lane * 4));
            const float4 a00 = __ldg(reinterpret_cast<const float4*>(easort + (size_t)j * 8));
            const float4 a01 = __ldg(reinterpret_cast<const float4*>(easort + (size_t)j * 8 + 4));
            const float4 a10 = __ldg(reinterpret_cast<const float4*>(easort + (size_t)(j + 1) * 8));
            const float4 a11 = __ldg(reinterpret_cast<const float4*>(easort + (size_t)(j + 1) * 8 + 4));
            const float k0[8] = {a00.x, a00.y, a00.z, a00.w, a01.x, a01.y, a01.z, a01.w};
            const float k1[8] = {a10.x, a10.y, a10.z, a10.w, a11.x, a11.y, a11.z, a11.w};
            float4 e0 = bb, e1 = bb;
#pragma unroll
            for (int k = 0; k < 8; k++) {
                e0.x = fmaf(k0[k], w[k].x, e0.x);
                e0.y = fmaf(k0[k], w[k].y, e0.y);
                e0.z = fmaf(k0[k], w[k].z, e0.z);
                e0.w = fmaf(k0[k], w[k].w, e0.w);
                e1.x = fmaf(k1[k], w[k].x, e1.x);
                e1.y = fmaf(k1[k], w[k].y, e1.y);
                e1.z = fmaf(k1[k], w[k].z, e1.z);
                e1.w = fmaf(k1[k], w[k].w, e1.w);
            }
            acc.x += fmaxf(hv0.x + e0.x, 0.f) + fmaxf(hv1.x + e1.x, 0.f);
            acc.y += fmaxf(hv0.y + e0.y, 0.f) + fmaxf(hv1.y + e1.y, 0.f);
            acc.z += fmaxf(hv0.z + e0.z, 0.f) + fmaxf(hv1.z + e1.z, 0.f);
            acc.w += fmaxf(hv0.w + e0.w, 0.f) + fmaxf(hv1.w + e1.w, 0.f);
        }
        if (j < o1) {
            const int s = __ldg(srcs + j);
            const float4 hv = __ldg(reinterpret_cast<const float4*>(hin + (size_t)s * DD + lane * 4));
            const float4 a0 = __ldg(reinterpret_cast<const float4*>(easort + (size_t)j * 8));
            const float4 a1 = __ldg(reinterpret_cast<const float4*>(easort + (size_t)j * 8 + 4));
            const float ak[8] = {a0.x, a0.y, a0.z, a0.w, a1.x, a1.y, a1.z, a1.w};
            float4 e = bb;
#pragma unroll
            for (int k = 0; k < 8; k++) {
                e.x = fmaf(ak[k], w[k].x, e.x);
                e.y = fmaf(ak[k], w[k].y, e.y);
                e.z = fmaf(ak[k], w[k].z, e.z);
                e.w = fmaf(ak[k], w[k].w, e.w);
            }
            acc.x += fmaxf(hv.x + e.x, 0.f);
            acc.y += fmaxf(hv.y + e.y, 0.f);
            acc.z += fmaxf(hv.z + e.z, 0.f);
            acc.w += fmaxf(hv.w + e.w, 0.f);
        }
        *reinterpret_cast<float4*>(zin + (size_t)d * DD + lane * 4) = acc;
    }
}

// ---------------- combined prep kernels (W tiles first, then A tiles) ----------
// z1 GEMM prep: W1 (F=HH, KT=DD/16) + A from row-major zin (K=DD)
__global__ void __launch_bounds__(256) prep_z1_kernel(
    const float* __restrict__ W, const float* __restrict__ A1,
    uint2* __restrict__ WFH, uint2* __restrict__ WFL,
    uint4* __restrict__ AFH, uint4* __restrict__ AFL,
    int M, int wtot, int total)
{
    int idx = blockIdx.x * 256 + threadIdx.x;
    if (idx >= total) return;
    const int KT = DD >> 4;                     // 8
    if (idx < wtot) {
        // ---- weight fragment (F = HH) ----
        const int lane = idx & 31;
        const int tile = idx >> 5;
        const int nt = tile / KT;
        const int kt = tile - nt * KT;
        const int n = nt * 8 + (lane >> 2);
        const int k0 = kt * 16 + (lane & 3) * 2;
        const float p00 = __ldg(W + (size_t)k0 * HH + n);
        const float p01 = __ldg(W + (size_t)(k0 + 1) * HH + n);
        const float p10 = __ldg(W + (size_t)(k0 + 8) * HH + n);
        const float p11 = __ldg(W + (size_t)(k0 + 9) * HH + n);
        uint2 hi, lo;
        pack2_split(p00, p01, hi.x, lo.x);
        pack2_split(p10, p11, hi.y, lo.y);
        WFH[tile * 32 + lane] = hi;
        WFL[tile * 32 + lane] = lo;
        return;
    }
    idx -= wtot;
    // ---- A fragment from row-major zin (MODE 2), K = DD ----
    const int lane = idx & 31;
    const int tile = idx >> 5;
    const int mt = tile / KT;
    const int kt = tile - mt * KT;
    const int g = lane >> 2;
    const int c = kt * 16 + (lane & 3) * 2;
    const int r0 = mt * 16 + g;

    float2 v[4];
    const int rr[4] = {r0, r0 + 8, r0, r0 + 8};
    const int cc[4] = {c, c, c + 8, c + 8};
#pragma unroll
    for (int i = 0; i < 4; i++) {
        float2 a = make_float2(0.f, 0.f);
        if (rr[i] < M)
            a = *reinterpret_cast<const float2*>(A1 + (size_t)rr[i] * DD + cc[i]);
        v[i] = a;
    }
    uint4 hi, lo;
    pack2_split(v[0].x, v[0].y, hi.x, lo.x);
    pack2_split(v[1].x, v[1].y, hi.y, lo.y);
    pack2_split(v[2].x, v[2].y, hi.z, lo.z);
    pack2_split(v[3].x, v[3].y, hi.w, lo.w);
    AFH[tile * 32 + lane] = hi;
    AFL[tile * 32 + lane] = lo;
}

// z2 GEMM prep: W2 (F=DD, KT=HH/16) + A from fragment-order z1f with BN+relu
__global__ void __launch_bounds__(256) prep_z2_kernel(
    const float* __restrict__ W, const float4* __restrict__ Zf,
    const float* __restrict__ sc, const float* __restrict__ sh,
    uint2* __restrict__ WFH, uint2* __restrict__ WFL,
    uint4* __restrict__ AFH, uint4* __restrict__ AFL,
    int wtot, int total)
{
    int idx = blockIdx.x * 256 + threadIdx.x;
    if (idx >= total) return;
    const int KT = HH >> 4;                     // 16
    if (idx < wtot) {
        // ---- weight fragment (F = DD) ----
        const int lane = idx & 31;
        const int tile = idx >> 5;
        const int nt = tile / KT;
        const int kt = tile - nt * KT;
        const int n = nt * 8 + (lane >> 2);
        const int k0 = kt * 16 + (lane & 3) * 2;
        const float p00 = __ldg(W + (size_t)k0 * DD + n);
        const float p01 = __ldg(W + (size_t)(k0 + 1) * DD + n);
        const float p10 = __ldg(W + (size_t)(k0 + 8) * DD + n);
        const float p11 = __ldg(W + (size_t)(k0 + 9) * DD + n);
        uint2 hi, lo;
        pack2_split(p00, p01, hi.x, lo.x);
        pack2_split(p10, p11, hi.y, lo.y);
        WFH[tile * 32 + lane] = hi;
        WFL[tile * 32 + lane] = lo;
        return;
    }
    idx -= wtot;
    // ---- A fragment from z1f (fragment-order), apply relu(scale*z+shift) ----
    const int NT = HH >> 3;                     // 32
    const int lane = idx & 31;
    const int tile = idx >> 5;
    const int mt = tile / KT;
    const int kt = tile - mt * KT;
    const int c0 = kt * 16 + (lane & 3) * 2;

    float4 v0 = __ldg(&Zf[((size_t)mt * NT + 2 * kt) * 32 + lane]);
    float4 v1 = __ldg(&Zf[((size_t)mt * NT + 2 * kt + 1) * 32 + lane]);
    const float2 s0 = *reinterpret_cast<const float2*>(sc + c0);
    const float2 t0 = *reinterpret_cast<const float2*>(sh + c0);
    const float2 s1 = *reinterpret_cast<const float2*>(sc + c0 + 8);
    const float2 t1 = *reinterpret_cast<const float2*>(sh + c0 + 8);
    v0.x = fmaxf(fmaf(s0.x, v0.x, t0.x), 0.f);
    v0.y = fmaxf(fmaf(s0.y, v0.y, t0.y), 0.f);
    v0.z = fmaxf(fmaf(s0.x, v0.z, t0.x), 0.f);
    v0.w = fmaxf(fmaf(s0.y, v0.w, t0.y), 0.f);
    v1.x = fmaxf(fmaf(s1.x, v1.x, t1.x), 0.f);
    v1.y = fmaxf(fmaf(s1.y, v1.y, t1.y), 0.f);
    v1.z = fmaxf(fmaf(s1.x, v1.z, t1.x), 0.f);
    v1.w = fmaxf(fmaf(s1.y, v1.w, t1.y), 0.f);

    uint4 hi, lo;
    pack2_split(v0.x, v0.y, hi.x, lo.x);
    pack2_split(v0.z, v0.w, hi.y, lo.y);
    pack2_split(v1.x, v1.y, hi.z, lo.z);
    pack2_split(v1.z, v1.w, hi.w, lo.w);
    AFH[tile * 32 + lane] = hi;
    AFL[tile * 32 + lane] = lo;
}

// ---------------- fragment-direct tensor-core GEMM ----------------------------
// FRAGOUT=1: store C in fragment order (float4 per lane per m16n8 tile)
template <int FDIM, int FRAGOUT>
__global__ void __launch_bounds__(256) frag_gemm(
    const uint4* __restrict__ AH, const uint4* __restrict__ AL,
    const uint2* __restrict__ BH, const uint2* __restrict__ BL,
    const float* __restrict__ bias, float* __restrict__ C, int M, int KT)
{
    const int lane = threadIdx.x & 31;
    const int wid = threadIdx.x >> 5;
    const int warp_m = wid & 3;
    const int warp_n = wid >> 2;
    const int mt0 = blockIdx.y * 8 + warp_m * 2;
    const int nt0 = blockIdx.x * 16 + warp_n * 8;

    float acc[2][8][4];
#pragma unroll
    for (int i = 0; i < 2; i++)
#pragma unroll
        for (int j = 0; j < 8; j++)
#pragma unroll
            for (int q = 0; q < 4; q++) acc[i][j][q] = 0.f;

    for (int kt = 0; kt < KT; kt++) {
        uint4 ah[2], al[2];
#pragma unroll
        for (int im = 0; im < 2; im++) {
            const size_t aidx = ((size_t)(mt0 + im) * KT + kt) * 32 + lane;
            ah[im] = __ldg(&AH[aidx]);
            al[im] = __ldg(&AL[aidx]);
        }
        uint2 bh[8], bl[8];
#pragma unroll
        for (int nb = 0; nb < 8; nb++) {
            const size_t bidx = ((size_t)(nt0 + nb) * KT + kt) * 32 + lane;
            bh[nb] = __ldg(&BH[bidx]);
            bl[nb] = __ldg(&BL[bidx]);
        }
#pragma unroll
        for (int im = 0; im < 2; im++)
#pragma unroll
            for (int nb = 0; nb < 8; nb++) {
                mma_bf16_v(acc[im][nb], reinterpret_cast<const uint32_t*>(&ah[im]),
                           reinterpret_cast<const uint32_t*>(&bh[nb]));
                mma_bf16_v(acc[im][nb], reinterpret_cast<const uint32_t*>(&ah[im]),
                           reinterpret_cast<const uint32_t*>(&bl[nb]));
                mma_bf16_v(acc[im][nb], reinterpret_cast<const uint32_t*>(&al[im]),
                           reinterpret_cast<const uint32_t*>(&bh[nb]));
            }
    }

    const int gid = lane >> 2;
    const int tig = lane & 3;
    if (FRAGOUT) {
        const int NT = FDIM / 8;
#pragma unroll
        for (int im = 0; im < 2; im++) {
            const int mt = mt0 + im;
#pragma unroll
            for (int nb = 0; nb < 8; nb++) {
                const int ntg = nt0 + nb;
                const int col = ntg * 8 + tig * 2;
                const float2 bv = *reinterpret_cast<const float2*>(bias + col);
                float4 o = make_float4(acc[im][nb][0] + bv.x, acc[im][nb][1] + bv.y,
                                       acc[im][nb][2] + bv.x, acc[im][nb][3] + bv.y);
                *reinterpret_cast<float4*>(C + (((size_t)mt * NT + ntg) * 32 + lane) * 4) = o;
            }
        }
    } else {
#pragma unroll
        for (int im = 0; im < 2; im++) {
            const int rbase = blockIdx.y * 128 + warp_m * 32 + im * 16;
            const int r0 = rbase + gid;
            const int r1 = r0 + 8;
#pragma unroll
            for (int nb = 0; nb < 8; nb++) {
                const int col = blockIdx.x * 128 + warp_n * 64 + nb * 8 + tig * 2;
                const float2 bv = *reinterpret_cast<const float2*>(bias + col);
                if (r0 < M) {
                    float2 o = make_float2(acc[im][nb][0] + bv.x, acc[im][nb][1] + bv.y);
                    *reinterpret_cast<float2*>(C + (size_t)r0 * FDIM + col) = o;
                }
                if (r1 < M) {
                    float2 o = make_float2(acc[im][nb][2] + bv.x, acc[im][nb][3] + bv.y);
                    *reinterpret_cast<float2*>(C + (size_t)r1 * FDIM + col) = o;
                }
            }
        }
    }
}

// ---------------- stats over fragment-order buffer -----------------------------
__global__ void __launch_bounds__(256) stats_frag_kernel(
    const float4* __restrict__ Zf, int M, int NT,
    float* __restrict__ gsum, float* __restrict__ gsq)
{
    const int nb = blockIdx.x;
    const int lane = threadIdx.x & 31;
    const int w = threadIdx.x >> 5;          // 8 warps
    const int tig = lane & 3;
    const int g = lane >> 2;
    const int mtfull = M >> 4;
    const int rem = M & 15;
    float s0 = 0.f, s1 = 0.f, q0 = 0.f, q1 = 0.f;
    for (int mt = blockIdx.y * 8 + w; mt < mtfull; mt += gridDim.y * 8) {
        const float4 v = __ldg(&Zf[((size_t)mt * NT + nb) * 32 + lane]);
        s0 += v.x + v.z; q0 = fmaf(v.x, v.x, fmaf(v.z, v.z, q0));
        s1 += v.y + v.w; q1 = fmaf(v.y, v.y, fmaf(v.w, v.w, q1));
    }
    if (rem && blockIdx.y == 0 && w == 0) {
        const float4 v = __ldg(&Zf[((size_t)mtfull * NT + nb) * 32 + lane]);
        if (g < rem)     { s0 += v.x; q0 = fmaf(v.x, v.x, q0); s1 += v.y; q1 = fmaf(v.y, v.y, q1); }
        if (g + 8 < rem) { s0 += v.z; q0 = fmaf(v.z, v.z, q0); s1 += v.w; q1 = fmaf(v.w, v.w, q1); }
    }
#pragma unroll
    for (int off = 4; off < 32; off <<= 1) {
        s0 += __shfl_xor_sync(0xffffffffu, s0, off);
        s1 += __shfl_xor_sync(0xffffffffu, s1, off);
        q0 += __shfl_xor_sync(0xffffffffu, q0, off);
        q1 += __shfl_xor_sync(0xffffffffu, q1, off);
    }
    __shared__ float sm[8][4][4];
    if (lane < 4) {
        sm[w][tig][0] = s0; sm[w][tig][1] = s1;
        sm[w][tig][2] = q0; sm[w][tig][3] = q1;
    }
    __syncthreads();
    if (threadIdx.x < 4) {
        const int t = threadIdx.x;
        float S0 = 0.f, S1 = 0.f, Q0 = 0.f, Q1 = 0.f;
#pragma unroll
        for (int ww = 0; ww < 8; ww++) {
            S0 += sm[ww][t][0]; S1 += sm[ww][t][1];
            Q0 += sm[ww][t][2]; Q1 += sm[ww][t][3];
        }
        const int col = nb * 8 + t * 2;
        atomicAdd(&gsum[col], S0);
        atomicAdd(&gsum[col + 1], S1);
        atomicAdd(&gsq[col], Q0);
        atomicAdd(&gsq[col + 1], Q1);
    }
}

// ---------------- elementwise / misc kernels ----------------------------------
// one-time init: vn broadcast, stats accumulators, AND pooled=0 (for layer 0)
__global__ void init_vn_kernel(const float* __restrict__ vn_emb, float* __restrict__ vn,
                               float* __restrict__ s, float* __restrict__ q,
                               float* __restrict__ pooled) {
    int idx = blockIdx.x * blockDim.x + threadIdx.x;
    if (idx < GG * DD) {
        vn[idx] = vn_emb[idx & (DD - 1)];
        pooled[idx] = 0.f;
    }
    if (idx < HH) { s[idx] = 0.f; q[idx] = 0.f; }
}

// h_in = op(A) + vn[batch];  POOL: pooled[batch] += h_in
template <int MODE, int POOL>
__global__ void hin_kernel(const float* __restrict__ A,
                           const float* __restrict__ sc, const float* __restrict__ sh,
                           const float* __restrict__ vn, const int* __restrict__ batch,
                           float* __restrict__ hin, float* __restrict__ pooled, int n) {
    int idx = blockIdx.x * blockDim.x + threadIdx.x;
    int total = n * (DD / 4);
    if (idx >= total) return;
    int row = idx >> 5;
    int c4 = (idx & 31) << 2;
    int g = batch[row];
    float4 a = *reinterpret_cast<const float4*>(A + (size_t)row * DD + c4);
    if (MODE == 1) {
        const float4 s = __ldg(reinterpret_cast<const float4*>(sc + c4));
        const float4 t = __ldg(reinterpret_cast<const float4*>(sh + c4));
        a.x = fmaxf(fmaf(s.x, a.x, t.x), 0.f);
        a.y = fmaxf(fmaf(s.y, a.y, t.y), 0.f);
        a.z = fmaxf(fmaf(s.z, a.z, t.z), 0.f);
        a.w = fmaxf(fmaf(s.w, a.w, t.w), 0.f);
    }
    const float4 b = *reinterpret_cast<const float4*>(vn + (size_t)g * DD + c4);
    float4 o = make_float4(a.x + b.x, a.y + b.y, a.z + b.z, a.w + b.w);
    *reinterpret_cast<float4*>(hin + (size_t)row * DD + c4) = o;
    if (POOL) atomic_add_f4(pooled + (size_t)g * DD + c4, o);
}

// SIMT GEMM for the tiny virtual-node MLPs (512 rows)
template <int MODE>
__global__ void __launch_bounds__(256) gemm_kernel(
    const float* __restrict__ A1, const float* __restrict__ A2,
    const float* __restrict__ bnscale, const float* __restrict__ bnshift,
    const float* __restrict__ B, const float* __restrict__ bias,
    float* __restrict__ C, int M, int K, int F)
{
    const int BM = 128, BN = 128, BK = 16;
    __shared__ float sA[BK][BM];
    __shared__ float sB[BK][BN];
    int tid = threadIdx.x;
    int brow = blockIdx.y * BM;
    int bcol = blockIdx.x * BN;

    float acc[8][8];
#pragma unroll
    for (int i = 0; i < 8; i++)
#pragma unroll
        for (int j = 0; j < 8; j++) acc[i][j] = 0.f;

    int tr = (tid >> 4) << 3;
    int tc = (tid & 15) << 3;

    for (int k0 = 0; k0 < K; k0 += BK) {
#pragma unroll
        for (int i = 0; i < 2; i++) {
            int idx = tid + i * 256;
            int r = idx >> 2;
            int c4 = (idx & 3) << 2;
            int row = brow + r;
            float4 v = make_float4(0.f, 0.f, 0.f, 0.f);
            if (row < M) {
                size_t off = (size_t)row * K + k0 + c4;
                if (MODE == 0) {
                    float4 a = __ldg(reinterpret_cast<const float4*>(A1 + off));
                    float4 b = __ldg(reinterpret_cast<const float4*>(A2 + off));
                    v = make_float4(a.x + b.x, a.y + b.y, a.z + b.z, a.w + b.w);
                } else {
                    float4 a = __ldg(reinterpret_cast<const float4*>(A1 + off));
                    float4 s = __ldg(reinterpret_cast<const float4*>(bnscale + k0 + c4));
                    float4 t = __ldg(reinterpret_cast<const float4*>(bnshift + k0 + c4));
                    v.x = fmaxf(fmaf(s.x, a.x, t.x), 0.f);
                    v.y = fmaxf(fmaf(s.y, a.y, t.y), 0.f);
                    v.z = fmaxf(fmaf(s.z, a.z, t.z), 0.f);
                    v.w = fmaxf(fmaf(s.w, a.w, t.w), 0.f);
                }
            }
            sA[c4 + 0][r] = v.x;
            sA[c4 + 1][r] = v.y;
            sA[c4 + 2][r] = v.z;
            sA[c4 + 3][r] = v.w;
        }
#pragma unroll
        for (int i = 0; i < 2; i++) {
            int idx = tid + i * 256;
            int r = idx >> 5;
            int c4 = (idx & 31) << 2;
            float4 v = __ldg(reinterpret_cast<const float4*>(B + (size_t)(k0 + r) * F + bcol + c4));
            *reinterpret_cast<float4*>(&sB[r][c4]) = v;
        }
        __syncthreads();
#pragma unroll
        for (int kk = 0; kk < BK; kk++) {
            float a[8], b[8];
            *reinterpret_cast<float4*>(&a[0]) = *reinterpret_cast<float4*>(&sA[kk][tr]);
            *reinterpret_cast<float4*>(&a[4]) = *reinterpret_cast<float4*>(&sA[kk][tr + 4]);
            *reinterpret_cast<float4*>(&b[0]) = *reinterpret_cast<float4*>(&sB[kk][tc]);
            *reinterpret_cast<float4*>(&b[4]) = *reinterpret_cast<float4*>(&sB[kk][tc + 4]);
#pragma unroll
            for (int i = 0; i < 8; i++)
#pragma unroll
                for (int j = 0; j < 8; j++)
                    acc[i][j] = fmaf(a[i], b[j], acc[i][j]);
        }
        __syncthreads();
    }
#pragma unroll
    for (int i = 0; i < 8; i++) {
        int row = brow + tr + i;
        if (row < M) {
#pragma unroll
            for (int j = 0; j < 8; j += 4) {
                float4 bv = __ldg(reinterpret_cast<const float4*>(bias + bcol + tc + j));
                float4 o;
                o.x = acc[i][j + 0] + bv.x;
                o.y = acc[i][j + 1] + bv.y;
                o.z = acc[i][j + 2] + bv.z;
                o.w = acc[i][j + 3] + bv.w;
                *reinterpret_cast<float4*>(C + (size_t)row * F + bcol + tc + j) = o;
            }
        }
    }
}

__global__ void stats_kernel(const float* __restrict__ Z, int M, int F,
                             float* __restrict__ gsum, float* __restrict__ gsq) {
    int col = threadIdx.x;
    int r0 = blockIdx.x * 128;
    int rend = min(r0 + 128, M);
    float s = 0.f, q = 0.f;
    for (int r = r0; r < rend; r++) {
        float v = Z[(size_t)r * F + col];
        s += v;
        q = fmaf(v, v, q);
    }
    atomicAdd(&gsum[col], s);
    atomicAdd(&gsq[col], q);
}

// consume stats, produce scale/shift, then zero the accumulators for reuse
__global__ void bn_finalize_kernel(float* __restrict__ gsum, float* __restrict__ gsq,
                                   const float* __restrict__ gamma, const float* __restrict__ beta,
                                   int M, float* __restrict__ scale, float* __restrict__ shift) {
    int f = threadIdx.x;
    float invM = 1.f / (float)M;
    float mean = gsum[f] * invM;
    float var = gsq[f] * invM - mean * mean;
    float inv = rsqrtf(var + BN_EPS);
    float sc = gamma[f] * inv;
    scale[f] = sc;
    shift[f] = beta[f] - mean * sc;
    gsum[f] = 0.f;
    gsq[f] = 0.f;
}

__global__ void bn_apply_kernel(const float* __restrict__ Z, const float* __restrict__ scale,
                                const float* __restrict__ shift, float* __restrict__ out,
                                int M, int F, int do_relu) {
    int idx = blockIdx.x * blockDim.x + threadIdx.x;
    int total = M * (F >> 2);
    if (idx >= total) return;
    int cols4 = F >> 2;
    int row = idx / cols4;
    int c4 = (idx - row * cols4) << 2;
    float4 z = *reinterpret_cast<const float4*>(Z + (size_t)row * F + c4);
    float4 s = __ldg(reinterpret_cast<const float4*>(scale + c4));
    float4 t = __ldg(reinterpret_cast<const float4*>(shift + c4));
    float4 o;
    o.x = fmaf(s.x, z.x, t.x);
    o.y = fmaf(s.y, z.y, t.y);
    o.z = fmaf(s.z, z.z, t.z);
    o.w = fmaf(s.w, z.w, t.w);
    if (do_relu) {
        o.x = fmaxf(o.x, 0.f);
        o.y = fmaxf(o.y, 0.f);
        o.z = fmaxf(o.z, 0.f);
        o.w = fmaxf(o.w, 0.f);
    }
    *reinterpret_cast<float4*>(out + (size_t)row * F + c4) = o;
}

// vn = relu(scale*Z + shift)  AND  pooled = 0 (prepares next layer's pooling)
__global__ void bn_apply_vn_kernel(const float* __restrict__ Z, const float* __restrict__ scale,
                                   const float* __restrict__ shift, float* __restrict__ vn,
                                   float* __restrict__ pooled) {
    int idx = blockIdx.x * blockDim.x + threadIdx.x;
    int total = GG * (DD >> 2);
    if (idx >= total) return;
    int row = idx >> 5;
    int c4 = (idx & 31) << 2;
    float4 z = *reinterpret_cast<const float4*>(Z + (size_t)row * DD + c4);
    float4 s = __ldg(reinterpret_cast<const float4*>(scale + c4));
    float4 t = __ldg(reinterpret_cast<const float4*>(shift + c4));
    float4 o;
    o.x = fmaxf(fmaf(s.x, z.x, t.x), 0.f);
    o.y = fmaxf(fmaf(s.y, z.y, t.y), 0.f);
    o.z = fmaxf(fmaf(s.z, z.z, t.z), 0.f);
    o.w = fmaxf(fmaf(s.w, z.w, t.w), 0.f);
    *reinterpret_cast<float4*>(vn + (size_t)row * DD + c4) = o;
    *reinterpret_cast<float4*>(pooled + (size_t)row * DD + c4) = make_float4(0.f, 0.f, 0.f, 0.f);
}

// ------------------------------ host driver ----------------------------------
static inline int cdiv(int a, int b) { return (a + b - 1) / b; }

extern "C" void kernel_launch(void* const* d_in, const int* in_sizes, int n_in,
                              void* d_out, int out_size) {
    const float* x        = (const float*)d_in[0];
    const float* edge_attr= (const float*)d_in[1];
    const float* vn_emb   = (const float*)d_in[2];
    const float* We   = (const float*)d_in[3];
    const float* be   = (const float*)d_in[4];
    const float* W1   = (const float*)d_in[5];
    const float* b1   = (const float*)d_in[6];
    const float* g1   = (const float*)d_in[7];
    const float* bt1  = (const float*)d_in[8];
    const float* W2   = (const float*)d_in[9];
    const float* b2   = (const float*)d_in[10];
    const float* gb   = (const float*)d_in[11];
    const float* bbp  = (const float*)d_in[12];
    const float* Wv1  = (const float*)d_in[13];
    const float* bv1  = (const float*)d_in[14];
    const float* gv1  = (const float*)d_in[15];
    const float* btv1 = (const float*)d_in[16];
    const float* Wv2  = (const float*)d_in[17];
    const float* bv2  = (const float*)d_in[18];
    const float* gv2  = (const float*)d_in[19];
    const float* btv2 = (const float*)d_in[20];
    const int* edge_index = (const int*)d_in[21];
    const int* batch      = (const int*)d_in[22];

    const int N = in_sizes[0] / DD;
    const int E = in_sizes[1] / 8;
    const int* srcp = edge_index;
    const int* dstp = edge_index + E;
    float* out = (float*)d_out;

    float *p_hin, *p_zin, *p_z1f, *p_z2, *p_vn, *p_pooled, *p_tv1, *p_tv2;
    float *p_sum, *p_sq, *p_scale, *p_shift, *p_scale2, *p_shift2, *p_easort;
    int *p_deg, *p_start, *p_cursor, *p_counter, *p_srcs;
    uint4 *p_fAH, *p_fAL;
    uint2 *p_fWH, *p_fWL;
    cudaGetSymbolAddress((void**)&p_hin, g_hin);
    cudaGetSymbolAddress((void**)&p_zin, g_zin);
    cudaGetSymbolAddress((void**)&p_z1f, g_z1f);
    cudaGetSymbolAddress((void**)&p_z2, g_z2);
    cudaGetSymbolAddress((void**)&p_vn, g_vn);
    cudaGetSymbolAddress((void**)&p_pooled, g_pooled);
    cudaGetSymbolAddress((void**)&p_tv1, g_tv1);
    cudaGetSymbolAddress((void**)&p_tv2, g_tv2);
    cudaGetSymbolAddress((void**)&p_sum, g_sum);
    cudaGetSymbolAddress((void**)&p_sq, g_sumsq);
    cudaGetSymbolAddress((void**)&p_scale, g_scale);
    cudaGetSymbolAddress((void**)&p_shift, g_shift);
    cudaGetSymbolAddress((void**)&p_scale2, g_scale2);
    cudaGetSymbolAddress((void**)&p_shift2, g_shift2);
    cudaGetSymbolAddress((void**)&p_easort, g_easort);
    cudaGetSymbolAddress((void**)&p_deg, g_deg);
    cudaGetSymbolAddress((void**)&p_start, g_start);
    cudaGetSymbolAddress((void**)&p_cursor, g_cursor);
    cudaGetSymbolAddress((void**)&p_counter, g_counter);
    cudaGetSymbolAddress((void**)&p_srcs, g_srcs);
    cudaGetSymbolAddress((void**)&p_fAH, g_fAH);
    cudaGetSymbolAddress((void**)&p_fAL, g_fAL);
    cudaGetSymbolAddress((void**)&p_fWH, g_fWH);
    cudaGetSymbolAddress((void**)&p_fWL, g_fWL);

    // ---- one-time per call: init vn + stats + pooled=0 + CSR build ----
    init_vn_kernel<<<cdiv(GG * DD, 256), 256>>>(vn_emb, p_vn, p_sum, p_sq, p_pooled);
    zero_deg_kernel<<<cdiv(N, 256), 256>>>(p_deg, p_counter, N);
    hist_kernel<<<cdiv(E, 256), 256>>>(dstp, p_deg, E);
    alloc_kernel<<<cdiv(N, 256), 256>>>(p_deg, p_start, p_cursor, p_counter, N);
    scatter_kernel<<<cdiv(E, 256), 256>>>(srcp, dstp, edge_attr, p_cursor,
                                          p_srcs, p_easort, E);

    const int nf4 = N * (DD / 4);
    const int KT1 = DD / 16;                        // 8
    const int KT2 = HH / 16;                        // 16
    const int wtot1 = (HH / 8) * KT1 * 32;          // 8192
    const int atot1 = MT_TILES * KT1 * 32;
    const int wtot2 = (DD / 8) * KT2 * 32;          // 8192
    const int atot2 = MT_TILES * KT2 * 32;

    for (int l = 0; l < LL; l++) {
        const int need_pool = (l < LL - 1);
        // h_in = op(prev) + vn[batch]; pooled[batch] += h_in
        if (l == 0) {
            if (need_pool)
                hin_kernel<0, 1><<<cdiv(nf4, 256), 256>>>(x, nullptr, nullptr, p_vn, batch,
                                                          p_hin, p_pooled, N);
            else
                hin_kernel<0, 0><<<cdiv(nf4, 256), 256>>>(x, nullptr, nullptr, p_vn, batch,
                                                          p_hin, p_pooled, N);
        } else {
            if (need_pool)
                hin_kernel<1, 1><<<cdiv(nf4, 256), 256>>>(p_z2, p_scale2, p_shift2, p_vn, batch,
                                                          p_hin, p_pooled, N);
            else
                hin_kernel<1, 0><<<cdiv(nf4, 256), 256>>>(p_z2, p_scale2, p_shift2, p_vn, batch,
                                                          p_hin, p_pooled, N);
        }
        // zin = h_in + sum_edges relu(h_in[src] + MLP(ea))   (atomic-free CSR)
        edge_aggr_kernel<<<2048, 256>>>(p_easort, We + (size_t)l * 8 * DD,
                                        be + (size_t)l * DD, p_hin, p_srcs, p_start,
                                        p_deg, p_zin, N);

        // ---- z1f = zin @ W1 + b1  (fragment-order output)  [N x HH], K=DD ----
        prep_z1_kernel<<<cdiv(wtot1 + atot1, 256), 256>>>(
            W1 + (size_t)l * DD * HH, p_zin, p_fWH, p_fWL, p_fAH, p_fAL,
            N, wtot1, wtot1 + atot1);
        {
            dim3 grid(HH / 128, GRID_ROWS);
            frag_gemm<HH, 1><<<grid, 256>>>(p_fAH, p_fAL, p_fWH, p_fWL,
                                            b1 + (size_t)l * HH, p_z1f, N, KT1);
        }
        {
            dim3 sgrid(HH / 8, 8);
            stats_frag_kernel<<<sgrid, 256>>>((const float4*)p_z1f, N, HH / 8, p_sum, p_sq);
        }
        bn_finalize_kernel<<<1, HH>>>(p_sum, p_sq, g1 + (size_t)l * HH, bt1 + (size_t)l * HH,
                                      N, p_scale, p_shift);

        // ---- z2 = relu(BN(z1)) @ W2 + b2    [N x DD], K=HH ----
        prep_z2_kernel<<<cdiv(wtot2 + atot2, 256), 256>>>(
            W2 + (size_t)l * HH * DD, (const float4*)p_z1f, p_scale, p_shift,
            p_fWH, p_fWL, p_fAH, p_fAL, wtot2, wtot2 + atot2);
        {
            dim3 grid(DD / 128, GRID_ROWS);
            frag_gemm<DD, 0><<<grid, 256>>>(p_fAH, p_fAL, p_fWH, p_fWL,
                                            b2 + (size_t)l * DD, p_z2, N, KT2);
        }
        stats_kernel<<<cdiv(N, 128), DD>>>(p_z2, N, DD, p_sum, p_sq);
        bn_finalize_kernel<<<1, DD>>>(p_sum, p_sq, gb + (size_t)l * DD, bbp + (size_t)l * DD,
                                      N, p_scale2, p_shift2);

        if (l < LL - 1) {
            // ---- virtual node update (tiny, SIMT path) ----
            {
                dim3 grid(HH / 128, cdiv(GG, 128));
                gemm_kernel<0><<<grid, 256>>>(p_pooled, p_vn, nullptr, nullptr,
                                              Wv1 + (size_t)l * DD * HH, bv1 + (size_t)l * HH,
                                              p_tv1, GG, DD, HH);
            }
            stats_kernel<<<cdiv(GG, 128), HH>>>(p_tv1, GG, HH, p_sum, p_sq);
            bn_finalize_kernel<<<1, HH>>>(p_sum, p_sq, gv1 + (size_t)l * HH, btv1 + (size_t)l * HH,
                                          GG, p_scale, p_shift);
            {
                dim3 grid(DD / 128, cdiv(GG, 128));
                gemm_kernel<1><<<grid, 256>>>(p_tv1, nullptr, p_scale, p_shift,
                                              Wv2 + (size_t)l * HH * DD, bv2 + (size_t)l * DD,
                                              p_tv2, GG, HH, DD);
            }
            stats_kernel<<<cdiv(GG, 128), DD>>>(p_tv2, GG, DD, p_sum, p_sq);
            bn_finalize_kernel<<<1, DD>>>(p_sum, p_sq, gv2 + (size_t)l * DD, btv2 + (size_t)l * DD,
                                          GG, p_scale, p_shift);
            // vn = relu(BN(tv2)); also re-zero pooled for the next layer's pooling
            bn_apply_vn_kernel<<<cdiv(GG * DD / 4, 256), 256>>>(p_tv2, p_scale, p_shift,
                                                                p_vn, p_pooled);
        } else {
            bn_apply_kernel<<<cdiv(nf4, 256), 256>>>(p_z2, p_scale2, p_shift2, out, N, DD, 0);
        }
    }
}